// round 8
// baseline (speedup 1.0000x reference)
#include <cuda_runtime.h>
#include <cuda_bf16.h>
#include <math.h>

#define NB   64
#define NP   196
#define NENC 512
#define NE   1024
#define NH   1024
#define NA   512
#define NV   20000
#define NT   24
#define NCAP 25
#define NLIN 5120          // [attdec 512 | gatepre 512 | gates 4096]
#define PRED_SIZE (NB*NT*NV)   /* 30,720,000 */
#define ALPHA_SIZE (NB*NT*NP)  /* 301,056 */

typedef unsigned long long u64;

// ---------------- device scratch (static; no allocations) ----------------
__device__ float g_att_enc[NB*NP*NA];     // 25.7 MB
__device__ float g_mean[NB*NENC];
__device__ float g_h[NB*NH];
__device__ float g_c[NB*NH];
__device__ float g_hall[NT*NB*NH];        // row = t*64 + b
__device__ float g_lin[NB*NLIN];          // bias-preloaded accumulator
__device__ float g_ctx[NB*NENC];          // gate*context
__device__ float g_emb[NT*NB*NE];         // pre-gathered embeddings, row = t*64+b
__device__ float g_biascat[NLIN];

// ---------------- helpers ----------------
__device__ __forceinline__ u64 pk2(float lo, float hi){
    u64 r; asm("mov.b64 %0,{%1,%2};" : "=l"(r) : "f"(lo), "f"(hi)); return r;
}
__device__ __forceinline__ void fma2(u64 &d, u64 a, u64 b){
    asm("fma.rn.f32x2 %0,%1,%2,%0;" : "+l"(d) : "l"(a), "l"(b));
}
__device__ __forceinline__ float2 up2(u64 v){
    float2 f; asm("mov.b64 {%0,%1},%2;" : "=f"(f.x), "=f"(f.y) : "l"(v)); return f;
}
__device__ __forceinline__ float sigm(float x){ return 1.0f/(1.0f+expf(-x)); }
__device__ __forceinline__ unsigned su(const void* p){
    return (unsigned)__cvta_generic_to_shared(p);
}
__device__ __forceinline__ void cp16(unsigned saddr, const void* g){
    asm volatile("cp.async.cg.shared.global [%0],[%1],16;" :: "r"(saddr), "l"(g));
}
__device__ __forceinline__ void cp16p(unsigned saddr, const void* g, int bytes){
    asm volatile("cp.async.cg.shared.global [%0],[%1],16,%2;" :: "r"(saddr), "l"(g), "r"(bytes));
}
__device__ __forceinline__ void cp_commit(){ asm volatile("cp.async.commit_group;"); }
__device__ __forceinline__ void cp_wait1(){ asm volatile("cp.async.wait_group 1;" ::: "memory"); }

// =====================================================================
// Tiled GEMM: C[M,N] = A[M,K] @ W[K,N] + bias.
// BM=BN=128, BK=16, 256 threads, 8x8 per thread, f32x2 accumulation.
// cp.async 2-stage double-buffered pipeline.
// cmode 0: plain row-major store.  cmode 1: logits scatter
//          (row m = t*64+b -> C[(b*NT+t)*NV + n]).
// Requires M%128==0, K%16==0, N%4==0.
// =====================================================================
__global__ void __launch_bounds__(256,2) gemm_tiled(
    const float* __restrict__ Am, const float* __restrict__ W,
    const float* __restrict__ bias, float* __restrict__ C,
    int M, int N, int K, int cmode)
{
    __shared__ __align__(16) float As[2][128][16];  // raw, row-major
    __shared__ __align__(16) float Bs[2][16][128];
    const int bm = blockIdx.y*128, bn = blockIdx.x*128;
    const int tid = threadIdx.x;
    const int ty = tid>>4, tx = tid&15;

    u64 acc[8][4];
    #pragma unroll
    for (int i=0;i<8;i++)
        #pragma unroll
        for (int j=0;j<4;j++) acc[i][j]=0ULL;

    const int KT = K>>4;

    auto load_stage = [&](int kt, int buf){
        int k0 = kt<<4;
        #pragma unroll
        for (int rep=0;rep<2;rep++){
            int i = tid + rep*256;
            int r = i>>2, q = i&3;
            cp16(su(&As[buf][r][q*4]), &Am[(size_t)(bm+r)*K + k0 + q*4]);
        }
        #pragma unroll
        for (int rep=0;rep<2;rep++){
            int i = tid + rep*256;
            int r = i>>5, c4 = i&31;
            int gcol = bn + c4*4;
            int inb  = (gcol < N);
            // clamp source address for the zero-fill (OOB) lanes so the
            // computed pointer always stays inside W
            size_t gi = (size_t)(k0+r)*N + (inb ? gcol : 0);
            cp16p(su(&Bs[buf][r][c4*4]), &W[gi], inb ? 16 : 0);
        }
    };

    load_stage(0, 0); cp_commit();

    for (int kt=0; kt<KT; kt++){
        if (kt+1 < KT) load_stage(kt+1, (kt+1)&1);
        cp_commit();
        cp_wait1();
        __syncthreads();
        const int buf = kt&1;
        #pragma unroll
        for (int kk=0;kk<16;kk++){
            u64 a2[8], b2[4];
            #pragma unroll
            for (int i=0;i<8;i++){
                float av = As[buf][ty*8 + i][kk];   // warp-broadcast LDS
                a2[i] = pk2(av, av);
            }
            #pragma unroll
            for (int u=0;u<2;u++){
                ulonglong2 t = *(const ulonglong2*)&Bs[buf][kk][tx*8 + u*4];
                b2[u*2]=t.x; b2[u*2+1]=t.y;
            }
            #pragma unroll
            for (int i=0;i<8;i++)
                #pragma unroll
                for (int j=0;j<4;j++) fma2(acc[i][j], a2[i], b2[j]);
        }
        __syncthreads();
    }

    #pragma unroll
    for (int i=0;i<8;i++){
        int m = bm + ty*8 + i;
        #pragma unroll
        for (int j=0;j<4;j++){
            int n0 = bn + tx*8 + j*2;
            if (n0 >= N) continue;
            float2 v = up2(acc[i][j]);
            float o0 = v.x + bias[n0], o1 = v.y + bias[n0+1];
            if (cmode==0){
                C[(size_t)m*N + n0]   = o0;
                C[(size_t)m*N + n0+1] = o1;
            } else {
                int b = m & 63, t = m >> 6;
                size_t base = ((size_t)(b*NT + t))*NV + n0;
                C[base]   = o0;
                C[base+1] = o1;
            }
        }
    }
}

// =====================================================================
// Recurrent small-M GEMM (M=64), BN=128, split-K, atomicAdd into a
// bias-preloaded destination. cp.async 2-stage pipeline.
// mode 0: h @ [W_dec_att | W_fbeta | W_hh] -> g_lin        grid(40,4)
// mode 1: [emb(t) | gate*ctx] @ W_ih -> g_lin[:,1024:]     grid(32,6)
// mode 2: mean @ W_init_h / W_init_c -> g_h / g_c          grid(8,2)
// =====================================================================
__global__ void __launch_bounds__(256) gemm_rec(
    const float* __restrict__ W0, const float* __restrict__ W1,
    const float* __restrict__ W2, int mode, int t)
{
    __shared__ __align__(16) float As[2][64][16];
    __shared__ __align__(16) float Bs[2][16][128];
    const int nt = blockIdx.x, kz = blockIdx.y;
    const int tid = threadIdx.x;

    const float *Ap, *Wp; float* dst;
    int lda, ldw, ldd, ak0, wk0, kc, wcol, dcol;
    if (mode==0){
        Ap=g_h; lda=NH; ak0=kz*256; wk0=ak0; kc=256; dst=g_lin; ldd=NLIN;
        int nc = nt*128; dcol=nc;
        if (nc<512)       { Wp=W0; wcol=nc;      ldw=512;  }
        else if (nc<1024) { Wp=W1; wcol=nc-512;  ldw=512;  }
        else              { Wp=W2; wcol=nc-1024; ldw=4096; }
    } else if (mode==1){
        kc=256; dst=g_lin; ldd=NLIN; Wp=W0; ldw=4096;
        wcol=nt*128; dcol=1024+nt*128;
        if (kz < 4){ Ap = g_emb + (size_t)t*NB*NE; lda=NE;   ak0=kz*256;     wk0=kz*256; }
        else       { Ap = g_ctx;                   lda=NENC; ak0=(kz-4)*256; wk0=1024+(kz-4)*256; }
    } else {
        Ap=g_mean; lda=NENC; ak0=0; wk0=0; kc=512; ldd=NH;
        Wp=(kz==0)?W0:W1; ldw=NH; wcol=nt*128; dcol=nt*128;
        dst=(kz==0)?g_h:g_c;
    }

    const int ty=tid>>5, tx=tid&31;
    u64 acc[8][2];
    #pragma unroll
    for (int i=0;i<8;i++){ acc[i][0]=0ULL; acc[i][1]=0ULL; }

    const int KT = kc>>4;

    auto load_stage = [&](int kt, int buf){
        int k = kt<<4;
        {
            int r = tid>>2, q = tid&3;
            cp16(su(&As[buf][r][q*4]), &Ap[(size_t)r*lda + ak0 + k + q*4]);
        }
        #pragma unroll
        for (int rep=0;rep<2;rep++){
            int i = tid + rep*256;
            int r = i>>5, c4 = i&31;
            cp16(su(&Bs[buf][r][c4*4]), &Wp[(size_t)(wk0+k+r)*ldw + wcol + c4*4]);
        }
    };

    load_stage(0,0); cp_commit();

    for (int kt=0; kt<KT; kt++){
        if (kt+1 < KT) load_stage(kt+1, (kt+1)&1);
        cp_commit();
        cp_wait1();
        __syncthreads();
        const int buf = kt&1;
        #pragma unroll
        for (int kk=0;kk<16;kk++){
            u64 a2[8];
            #pragma unroll
            for (int i=0;i<8;i++){
                float av = As[buf][ty*8 + i][kk];
                a2[i] = pk2(av, av);
            }
            ulonglong2 bt = *(const ulonglong2*)&Bs[buf][kk][tx*4];
            #pragma unroll
            for (int i=0;i<8;i++){ fma2(acc[i][0], a2[i], bt.x); fma2(acc[i][1], a2[i], bt.y); }
        }
        __syncthreads();
    }

    #pragma unroll
    for (int i=0;i<8;i++){
        int m = ty*8 + i;
        float* dp = dst + (size_t)m*ldd + dcol + tx*4;
        float2 v0 = up2(acc[i][0]), v1 = up2(acc[i][1]);
        atomicAdd(dp+0, v0.x); atomicAdd(dp+1, v0.y);
        atomicAdd(dp+2, v1.x); atomicAdd(dp+3, v1.y);
    }
}

// ---------------- small kernels ----------------
__global__ void biascat_kernel(const float* __restrict__ b_dec, const float* __restrict__ b_fb,
                               const float* __restrict__ b_ih, const float* __restrict__ b_hh){
    int i = blockIdx.x*256 + threadIdx.x;
    if (i < 512)       g_biascat[i] = b_dec[i];
    else if (i < 1024) g_biascat[i] = b_fb[i-512];
    else if (i < NLIN) g_biascat[i] = b_ih[i-1024] + b_hh[i-1024];
}

__global__ void lin_init_kernel(){
    int b = blockIdx.x;
    for (int i=threadIdx.x; i<NLIN; i+=256) g_lin[b*NLIN + i] = g_biascat[i];
}

__global__ void mean_kernel(const float* __restrict__ enc){
    int b = blockIdx.x;
    int e = blockIdx.y*128 + threadIdx.x;
    const float* p = enc + (size_t)b*NP*NENC + e;
    float s = 0.f;
    #pragma unroll 4
    for (int i=0;i<NP;i++) s += p[(size_t)i*NENC];
    g_mean[b*NENC + e] = s * (1.0f/(float)NP);
}

__global__ void init_hc_kernel(const float* __restrict__ bh, const float* __restrict__ bc){
    int b = blockIdx.x;
    int n = blockIdx.y*256 + threadIdx.x;
    g_h[b*NH + n] = bh[n];
    g_c[b*NH + n] = bc[n];
}

__global__ void emb_gather_kernel(const float* __restrict__ emb, const int* __restrict__ cap){
    int tb = blockIdx.x;                 // t*64 + b
    int t = tb>>6, b = tb&63;
    int tok = cap[b*NCAP + t];
    const float4* src = (const float4*)(emb + (size_t)tok*NE);
    float4* dst = (float4*)(g_emb + (size_t)tb*NE);
    dst[threadIdx.x] = src[threadIdx.x];  // 256 x float4 = 1024 floats
}

// Fused attention: energy -> softmax -> gated context.  grid(64), 256 thr.
__global__ void att_fused_kernel(const float* __restrict__ enc,
                                 const float* __restrict__ Wfull,
                                 const float* __restrict__ bfull,
                                 float* __restrict__ aout, int t){
    int b = blockIdx.x, tid = threadIdx.x;
    int warp = tid>>5, lane = tid&31;
    __shared__ float s_ad[NA], s_w[NA];
    __shared__ float s_en[NP], s_al[NP];
    __shared__ float red[8];
    __shared__ float sh_m, sh_s;

    for (int i=tid; i<NA; i+=256){
        s_ad[i] = g_lin[b*NLIN + i];
        s_w[i]  = Wfull[i];
    }
    __syncthreads();

    float bf = bfull[0];
    for (int p=warp; p<NP; p+=8){
        const float* ae = g_att_enc + (size_t)(b*NP + p)*NA;
        float s = 0.f;
        #pragma unroll 4
        for (int a=lane; a<NA; a+=32){
            float v = ae[a] + s_ad[a];
            v = fmaxf(v, 0.f);
            s += v * s_w[a];
        }
        #pragma unroll
        for (int o=16;o;o>>=1) s += __shfl_xor_sync(0xffffffffu, s, o);
        if (!lane) s_en[p] = s + bf;
    }
    __syncthreads();

    float v = (tid<NP) ? s_en[tid] : -3.4e38f;
    float m = v;
    #pragma unroll
    for (int o=16;o;o>>=1) m = fmaxf(m, __shfl_xor_sync(0xffffffffu, m, o));
    if (!lane) red[warp] = m;
    __syncthreads();
    if (tid==0){
        float mm = red[0];
        #pragma unroll
        for (int i=1;i<8;i++) mm = fmaxf(mm, red[i]);
        sh_m = mm;
    }
    __syncthreads();
    float e = (tid<NP) ? expf(v - sh_m) : 0.f;
    float s = e;
    #pragma unroll
    for (int o=16;o;o>>=1) s += __shfl_xor_sync(0xffffffffu, s, o);
    if (!lane) red[warp] = s;
    __syncthreads();
    if (tid==0){
        float ss = 0.f;
        #pragma unroll
        for (int i=0;i<8;i++) ss += red[i];
        sh_s = ss;
    }
    __syncthreads();
    float inv = 1.0f/sh_s;
    if (tid < NP){
        float a = e*inv;
        s_al[tid] = a;
        if (aout) aout[((size_t)b*NT + t)*NP + tid] = a;
    }
    __syncthreads();

    int e0 = tid*2;
    const float* pbase = enc + (size_t)b*NP*NENC + e0;
    float c0=0.f, c1=0.f;
    #pragma unroll 4
    for (int p=0;p<NP;p++){
        float2 w = *(const float2*)(pbase + (size_t)p*NENC);
        float al = s_al[p];
        c0 += al*w.x; c1 += al*w.y;
    }
    float g0 = sigm(g_lin[b*NLIN + 512 + e0]);
    float g1 = sigm(g_lin[b*NLIN + 512 + e0 + 1]);
    g_ctx[b*NENC + e0]   = g0*c0;
    g_ctx[b*NENC + e0+1] = g1*c1;
}

// LSTM cell + reset g_lin (bias preload) for the next step
__global__ void lstm_kernel(int t){
    int b = blockIdx.x, tid = threadIdx.x;
    const float* L = g_lin + (size_t)b*NLIN + 1024;
    for (int n=tid; n<NH; n+=256){
        float iv = sigm(L[n]);
        float fv = sigm(L[1024+n]);
        float gv = tanhf(L[2048+n]);
        float ov = sigm(L[3072+n]);
        float c = fv*g_c[b*NH+n] + iv*gv;
        float h = ov*tanhf(c);
        g_c[b*NH+n] = c;
        g_h[b*NH+n] = h;
        g_hall[((size_t)t*NB + b)*NH + n] = h;
    }
    __syncthreads();
    for (int i=tid; i<NLIN; i+=256) g_lin[b*NLIN + i] = g_biascat[i];
}

// ---------------- launch ----------------
extern "C" void kernel_launch(void* const* d_in, const int* in_sizes, int n_in,
                              void* d_out, int out_size) {
    // order: encoder_out, captions, [lengths], W_enc_att, b_enc_att, W_dec_att,
    // b_dec_att, W_full_att, b_full_att, emb_table, W_ih, b_ih, W_hh, b_hh,
    // W_init_h, b_init_h, W_init_c, b_init_c, W_fbeta, b_fbeta, W_fc, b_fc
    int o = (n_in >= 22 && in_sizes[2] == 1) ? 1 : 0;
    const float* enc      = (const float*)d_in[0];
    const int*   cap      = (const int*)  d_in[1];
    const float* W_enc    = (const float*)d_in[2+o];
    const float* b_enc    = (const float*)d_in[3+o];
    const float* W_dec    = (const float*)d_in[4+o];
    const float* b_dec    = (const float*)d_in[5+o];
    const float* W_full   = (const float*)d_in[6+o];
    const float* b_full   = (const float*)d_in[7+o];
    const float* emb      = (const float*)d_in[8+o];
    const float* W_ih     = (const float*)d_in[9+o];
    const float* b_ih     = (const float*)d_in[10+o];
    const float* W_hh     = (const float*)d_in[11+o];
    const float* b_hh     = (const float*)d_in[12+o];
    const float* W_init_h = (const float*)d_in[13+o];
    const float* b_init_h = (const float*)d_in[14+o];
    const float* W_init_c = (const float*)d_in[15+o];
    const float* b_init_c = (const float*)d_in[16+o];
    const float* W_fbeta  = (const float*)d_in[17+o];
    const float* b_fbeta  = (const float*)d_in[18+o];
    const float* W_fc     = (const float*)d_in[19+o];
    const float* b_fc     = (const float*)d_in[20+o];

    float* preds = (float*)d_out;
    float* aout  = (out_size >= PRED_SIZE + ALPHA_SIZE) ? (preds + PRED_SIZE) : nullptr;

    float *p_att_enc=nullptr, *p_hall=nullptr;
    cudaGetSymbolAddress((void**)&p_att_enc, g_att_enc);
    cudaGetSymbolAddress((void**)&p_hall,    g_hall);

    // Setup
    biascat_kernel<<<20,256>>>(b_dec, b_fbeta, b_ih, b_hh);
    lin_init_kernel<<<NB,256>>>();
    mean_kernel<<<dim3(NB,4),128>>>(enc);
    init_hc_kernel<<<dim3(NB,4),256>>>(b_init_h, b_init_c);
    gemm_rec<<<dim3(8,2),256>>>(W_init_h, W_init_c, nullptr, 2, 0);
    emb_gather_kernel<<<NT*NB,256>>>(emb, cap);
    // att_enc = encoder_out @ W_enc_att + b_enc_att  (12544 x 512 x 512)
    gemm_tiled<<<dim3(4,98),256>>>(enc, W_enc, b_enc, p_att_enc, NB*NP, NA, NENC, 0);

    // Recurrence: 4 launches/step
    for (int t=0; t<NT; t++){
        gemm_rec<<<dim3(40,4),256>>>(W_dec, W_fbeta, W_hh, 0, t);
        att_fused_kernel<<<NB,256>>>(enc, W_full, b_full, aout, t);
        gemm_rec<<<dim3(32,6),256>>>(W_ih, nullptr, nullptr, 1, t);
        lstm_kernel<<<NB,256>>>(t);
    }

    // Final logits GEMM: g_hall(1536x1024) @ W_fc(1024x20000) + b_fc
    gemm_tiled<<<dim3(157,12),256>>>(p_hall, W_fc, b_fc, preds, NT*NB, NV, NH, 1);
}

// round 10
// speedup vs baseline: 1.0276x; 1.0276x over previous
#include <cuda_runtime.h>
#include <cuda_bf16.h>
#include <math.h>

#define NB   64
#define NP   196
#define NENC 512
#define NE   1024
#define NH   1024
#define NA   512
#define NV   20000
#define NT   24
#define NCAP 25
#define NLIN 5120          // [attdec 512 | gatepre 512 | gates 4096]
#define NM   (NT*NB)       /* 1536 */
#define PRED_SIZE (NB*NT*NV)   /* 30,720,000 */
#define ALPHA_SIZE (NB*NT*NP)  /* 301,056 */

typedef unsigned long long u64;

// ---------------- device scratch (static; no allocations) ----------------
__device__ float g_att_enc[NB*NP*NA];     // 25.7 MB
__device__ float g_encT[NENC*NB*NP];      // 25.7 MB  encoder_out transposed [ENC][B*P]
__device__ float g_mean[NB*NENC];
__device__ float g_h[NB*NH];
__device__ float g_c[NB*NH];
__device__ float g_hallT[NH*NM];          // 6 MB  hidden states TRANSPOSED [H][t*64+b]
__device__ float g_lin[NB*NLIN];          // bias-preloaded accumulator
__device__ float g_ctx[NB*NENC];          // gate*context
__device__ float g_emb[NT*NB*NE];         // pre-gathered embeddings, row = t*64+b
__device__ float g_biascat[NLIN];

// ---------------- helpers ----------------
__device__ __forceinline__ u64 pk2(float lo, float hi){
    u64 r; asm("mov.b64 %0,{%1,%2};" : "=l"(r) : "f"(lo), "f"(hi)); return r;
}
__device__ __forceinline__ void fma2(u64 &d, u64 a, u64 b){
    asm("fma.rn.f32x2 %0,%1,%2,%0;" : "+l"(d) : "l"(a), "l"(b));
}
__device__ __forceinline__ float2 up2(u64 v){
    float2 f; asm("mov.b64 {%0,%1},%2;" : "=f"(f.x), "=f"(f.y) : "l"(v)); return f;
}
__device__ __forceinline__ float sigm(float x){ return 1.0f/(1.0f+expf(-x)); }
__device__ __forceinline__ unsigned su(const void* p){
    return (unsigned)__cvta_generic_to_shared(p);
}
__device__ __forceinline__ void cp16(unsigned saddr, const void* g){
    asm volatile("cp.async.cg.shared.global [%0],[%1],16;" :: "r"(saddr), "l"(g));
}
__device__ __forceinline__ void cp16p(unsigned saddr, const void* g, int bytes){
    asm volatile("cp.async.cg.shared.global [%0],[%1],16,%2;" :: "r"(saddr), "l"(g), "r"(bytes));
}
__device__ __forceinline__ void cp_commit(){ asm volatile("cp.async.commit_group;"); }
__device__ __forceinline__ void cp_wait1(){ asm volatile("cp.async.wait_group 1;" ::: "memory"); }

// =====================================================================
// Tiled GEMM with TRANSPOSED A: C[M,N] = AT^T[M,K] @ W[K,N] + bias.
// AT is [K][M] so both A and B k-tiles are contiguous for cp.async, and
// the inner loop reads A via 2 broadcast LDS.128 instead of 8 conflicted
// scalar LDS (crossbar 6144 -> ~3072 cyc/tile < 4096 FFMA2 cyc -> fma-bound).
// BM=BN=128, BK=16, 256 threads, 8x8 per thread, f32x2 accumulation.
// cmode 0: plain row-major store.  cmode 1: logits scatter
//          (row m = t*64+b -> C[(b*NT+t)*NV + n]).
// Requires M%128==0, K%16==0, N%4==0.
// =====================================================================
__global__ void __launch_bounds__(256,2) gemm_tiled(
    const float* __restrict__ AT, const float* __restrict__ W,
    const float* __restrict__ bias, float* __restrict__ C,
    int M, int N, int K, int cmode)
{
    __shared__ __align__(16) float AsT[2][16][128];  // [kk][m]
    __shared__ __align__(16) float Bs[2][16][128];   // [kk][n]
    const int bm = blockIdx.y*128, bn = blockIdx.x*128;
    const int tid = threadIdx.x;
    const int ty = tid>>4, tx = tid&15;

    u64 acc[8][4];
    #pragma unroll
    for (int i=0;i<8;i++)
        #pragma unroll
        for (int j=0;j<4;j++) acc[i][j]=0ULL;

    const int KT = K>>4;

    auto load_stage = [&](int kt, int buf){
        int k0 = kt<<4;
        #pragma unroll
        for (int rep=0;rep<2;rep++){
            int i = tid + rep*256;          // 0..511
            int r = i>>5, c4 = i&31;
            cp16(su(&AsT[buf][r][c4*4]), &AT[(size_t)(k0+r)*M + bm + c4*4]);
        }
        #pragma unroll
        for (int rep=0;rep<2;rep++){
            int i = tid + rep*256;
            int r = i>>5, c4 = i&31;
            int gcol = bn + c4*4;
            int inb  = (gcol < N);
            // clamp source address for the zero-fill (OOB) lanes
            size_t gi = (size_t)(k0+r)*N + (inb ? gcol : 0);
            cp16p(su(&Bs[buf][r][c4*4]), &W[gi], inb ? 16 : 0);
        }
    };

    load_stage(0, 0); cp_commit();

    for (int kt=0; kt<KT; kt++){
        if (kt+1 < KT) load_stage(kt+1, (kt+1)&1);
        cp_commit();
        cp_wait1();
        __syncthreads();
        const int buf = kt&1;
        #pragma unroll
        for (int kk=0;kk<16;kk++){
            u64 a2[8], b2[4];
            {   // A: 2 broadcast LDS.128 (one address per half-warp)
                float4 a0 = *(const float4*)&AsT[buf][kk][ty*8];
                float4 a1 = *(const float4*)&AsT[buf][kk][ty*8+4];
                a2[0]=pk2(a0.x,a0.x); a2[1]=pk2(a0.y,a0.y);
                a2[2]=pk2(a0.z,a0.z); a2[3]=pk2(a0.w,a0.w);
                a2[4]=pk2(a1.x,a1.x); a2[5]=pk2(a1.y,a1.y);
                a2[6]=pk2(a1.z,a1.z); a2[7]=pk2(a1.w,a1.w);
            }
            #pragma unroll
            for (int u=0;u<2;u++){
                ulonglong2 t = *(const ulonglong2*)&Bs[buf][kk][tx*8 + u*4];
                b2[u*2]=t.x; b2[u*2+1]=t.y;
            }
            #pragma unroll
            for (int i=0;i<8;i++)
                #pragma unroll
                for (int j=0;j<4;j++) fma2(acc[i][j], a2[i], b2[j]);
        }
        __syncthreads();
    }

    #pragma unroll
    for (int i=0;i<8;i++){
        int m = bm + ty*8 + i;
        #pragma unroll
        for (int j=0;j<4;j++){
            int n0 = bn + tx*8 + j*2;
            if (n0 >= N) continue;
            float2 v = up2(acc[i][j]);
            float o0 = v.x + bias[n0], o1 = v.y + bias[n0+1];
            if (cmode==0){
                C[(size_t)m*N + n0]   = o0;
                C[(size_t)m*N + n0+1] = o1;
            } else {
                int b = m & 63, t = m >> 6;
                size_t base = ((size_t)(b*NT + t))*NV + n0;
                C[base]   = o0;
                C[base+1] = o1;
            }
        }
    }
}

// =====================================================================
// Recurrent small-M GEMM (M=64), BN=128, split-K, atomicAdd into a
// bias-preloaded destination. cp.async 2-stage pipeline.
// mode 0: h @ [W_dec_att | W_fbeta | W_hh] -> g_lin        grid(40,4)
// mode 1: [emb(t) | gate*ctx] @ W_ih -> g_lin[:,1024:]     grid(32,6)
// mode 2: mean @ W_init_h / W_init_c -> g_h / g_c          grid(8,2)
// =====================================================================
__global__ void __launch_bounds__(256) gemm_rec(
    const float* __restrict__ W0, const float* __restrict__ W1,
    const float* __restrict__ W2, int mode, int t)
{
    __shared__ __align__(16) float As[2][64][16];
    __shared__ __align__(16) float Bs[2][16][128];
    const int nt = blockIdx.x, kz = blockIdx.y;
    const int tid = threadIdx.x;

    const float *Ap, *Wp; float* dst;
    int lda, ldw, ldd, ak0, wk0, kc, wcol, dcol;
    if (mode==0){
        Ap=g_h; lda=NH; ak0=kz*256; wk0=ak0; kc=256; dst=g_lin; ldd=NLIN;
        int nc = nt*128; dcol=nc;
        if (nc<512)       { Wp=W0; wcol=nc;      ldw=512;  }
        else if (nc<1024) { Wp=W1; wcol=nc-512;  ldw=512;  }
        else              { Wp=W2; wcol=nc-1024; ldw=4096; }
    } else if (mode==1){
        kc=256; dst=g_lin; ldd=NLIN; Wp=W0; ldw=4096;
        wcol=nt*128; dcol=1024+nt*128;
        if (kz < 4){ Ap = g_emb + (size_t)t*NB*NE; lda=NE;   ak0=kz*256;     wk0=kz*256; }
        else       { Ap = g_ctx;                   lda=NENC; ak0=(kz-4)*256; wk0=1024+(kz-4)*256; }
    } else {
        Ap=g_mean; lda=NENC; ak0=0; wk0=0; kc=512; ldd=NH;
        Wp=(kz==0)?W0:W1; ldw=NH; wcol=nt*128; dcol=nt*128;
        dst=(kz==0)?g_h:g_c;
    }

    const int ty=tid>>5, tx=tid&31;
    u64 acc[8][2];
    #pragma unroll
    for (int i=0;i<8;i++){ acc[i][0]=0ULL; acc[i][1]=0ULL; }

    const int KT = kc>>4;

    auto load_stage = [&](int kt, int buf){
        int k = kt<<4;
        {
            int r = tid>>2, q = tid&3;
            cp16(su(&As[buf][r][q*4]), &Ap[(size_t)r*lda + ak0 + k + q*4]);
        }
        #pragma unroll
        for (int rep=0;rep<2;rep++){
            int i = tid + rep*256;
            int r = i>>5, c4 = i&31;
            cp16(su(&Bs[buf][r][c4*4]), &Wp[(size_t)(wk0+k+r)*ldw + wcol + c4*4]);
        }
    };

    load_stage(0,0); cp_commit();

    for (int kt=0; kt<KT; kt++){
        if (kt+1 < KT) load_stage(kt+1, (kt+1)&1);
        cp_commit();
        cp_wait1();
        __syncthreads();
        const int buf = kt&1;
        #pragma unroll
        for (int kk=0;kk<16;kk++){
            u64 a2[8];
            #pragma unroll
            for (int i=0;i<8;i++){
                float av = As[buf][ty*8 + i][kk];
                a2[i] = pk2(av, av);
            }
            ulonglong2 bt = *(const ulonglong2*)&Bs[buf][kk][tx*4];
            #pragma unroll
            for (int i=0;i<8;i++){ fma2(acc[i][0], a2[i], bt.x); fma2(acc[i][1], a2[i], bt.y); }
        }
        __syncthreads();
    }

    #pragma unroll
    for (int i=0;i<8;i++){
        int m = ty*8 + i;
        float* dp = dst + (size_t)m*ldd + dcol + tx*4;
        float2 v0 = up2(acc[i][0]), v1 = up2(acc[i][1]);
        atomicAdd(dp+0, v0.x); atomicAdd(dp+1, v0.y);
        atomicAdd(dp+2, v1.x); atomicAdd(dp+3, v1.y);
    }
}

// ---------------- small kernels ----------------
__global__ void biascat_kernel(const float* __restrict__ b_dec, const float* __restrict__ b_fb,
                               const float* __restrict__ b_ih, const float* __restrict__ b_hh){
    int i = blockIdx.x*256 + threadIdx.x;
    if (i < 512)       g_biascat[i] = b_dec[i];
    else if (i < 1024) g_biascat[i] = b_fb[i-512];
    else if (i < NLIN) g_biascat[i] = b_ih[i-1024] + b_hh[i-1024];
}

__global__ void lin_init_kernel(){
    int b = blockIdx.x;
    for (int i=threadIdx.x; i<NLIN; i+=256) g_lin[b*NLIN + i] = g_biascat[i];
}

__global__ void mean_kernel(const float* __restrict__ enc){
    int b = blockIdx.x;
    int e = blockIdx.y*128 + threadIdx.x;
    const float* p = enc + (size_t)b*NP*NENC + e;
    float s = 0.f;
    #pragma unroll 4
    for (int i=0;i<NP;i++) s += p[(size_t)i*NENC];
    g_mean[b*NENC + e] = s * (1.0f/(float)NP);
}

__global__ void init_hc_kernel(const float* __restrict__ bh, const float* __restrict__ bc){
    int b = blockIdx.x;
    int n = blockIdx.y*256 + threadIdx.x;
    g_h[b*NH + n] = bh[n];
    g_c[b*NH + n] = bc[n];
}

// Tiled transpose: out[C][R] = in[R][C].  R,C multiples of 32. grid(C/32, R/32), 256 thr.
__global__ void transpose_kernel(const float* __restrict__ in, float* __restrict__ out,
                                 int R, int C){
    __shared__ float tile[32][33];
    int cb = blockIdx.x*32, rb = blockIdx.y*32;
    int tx = threadIdx.x&31, ty = threadIdx.x>>5;   // 32 x 8
    #pragma unroll
    for (int j=0;j<32;j+=8)
        tile[ty+j][tx] = in[(size_t)(rb+ty+j)*C + cb+tx];
    __syncthreads();
    #pragma unroll
    for (int j=0;j<32;j+=8)
        out[(size_t)(cb+ty+j)*R + rb+tx] = tile[tx][ty+j];
}

__global__ void emb_gather_kernel(const float* __restrict__ emb, const int* __restrict__ cap){
    int tb = blockIdx.x;                 // t*64 + b
    int t = tb>>6, b = tb&63;
    int tok = cap[b*NCAP + t];
    const float4* src = (const float4*)(emb + (size_t)tok*NE);
    float4* dst = (float4*)(g_emb + (size_t)tb*NE);
    dst[threadIdx.x] = src[threadIdx.x];  // 256 x float4 = 1024 floats
}

// Fused attention: energy -> softmax -> gated context.  grid(64), 256 thr.
__global__ void att_fused_kernel(const float* __restrict__ enc,
                                 const float* __restrict__ Wfull,
                                 const float* __restrict__ bfull,
                                 float* __restrict__ aout, int t){
    int b = blockIdx.x, tid = threadIdx.x;
    int warp = tid>>5, lane = tid&31;
    __shared__ float s_ad[NA], s_w[NA];
    __shared__ float s_en[NP], s_al[NP];
    __shared__ float red[8];
    __shared__ float sh_m, sh_s;

    for (int i=tid; i<NA; i+=256){
        s_ad[i] = g_lin[b*NLIN + i];
        s_w[i]  = Wfull[i];
    }
    __syncthreads();

    float bf = bfull[0];
    for (int p=warp; p<NP; p+=8){
        const float* ae = g_att_enc + (size_t)(b*NP + p)*NA;
        float s = 0.f;
        #pragma unroll 4
        for (int a=lane; a<NA; a+=32){
            float v = ae[a] + s_ad[a];
            v = fmaxf(v, 0.f);
            s += v * s_w[a];
        }
        #pragma unroll
        for (int o=16;o;o>>=1) s += __shfl_xor_sync(0xffffffffu, s, o);
        if (!lane) s_en[p] = s + bf;
    }
    __syncthreads();

    float v = (tid<NP) ? s_en[tid] : -3.4e38f;
    float m = v;
    #pragma unroll
    for (int o=16;o;o>>=1) m = fmaxf(m, __shfl_xor_sync(0xffffffffu, m, o));
    if (!lane) red[warp] = m;
    __syncthreads();
    if (tid==0){
        float mm = red[0];
        #pragma unroll
        for (int i=1;i<8;i++) mm = fmaxf(mm, red[i]);
        sh_m = mm;
    }
    __syncthreads();
    float e = (tid<NP) ? expf(v - sh_m) : 0.f;
    float s = e;
    #pragma unroll
    for (int o=16;o;o>>=1) s += __shfl_xor_sync(0xffffffffu, s, o);
    if (!lane) red[warp] = s;
    __syncthreads();
    if (tid==0){
        float ss = 0.f;
        #pragma unroll
        for (int i=0;i<8;i++) ss += red[i];
        sh_s = ss;
    }
    __syncthreads();
    float inv = 1.0f/sh_s;
    if (tid < NP){
        float a = e*inv;
        s_al[tid] = a;
        if (aout) aout[((size_t)b*NT + t)*NP + tid] = a;
    }
    __syncthreads();

    int e0 = tid*2;
    const float* pbase = enc + (size_t)b*NP*NENC + e0;
    float c0=0.f, c1=0.f;
    #pragma unroll 4
    for (int p=0;p<NP;p++){
        float2 w = *(const float2*)(pbase + (size_t)p*NENC);
        float al = s_al[p];
        c0 += al*w.x; c1 += al*w.y;
    }
    float g0 = sigm(g_lin[b*NLIN + 512 + e0]);
    float g1 = sigm(g_lin[b*NLIN + 512 + e0 + 1]);
    g_ctx[b*NENC + e0]   = g0*c0;
    g_ctx[b*NENC + e0+1] = g1*c1;
}

// LSTM cell (h written TRANSPOSED into g_hallT) + reset g_lin for next step
__global__ void lstm_kernel(int t){
    int b = blockIdx.x, tid = threadIdx.x;
    const float* L = g_lin + (size_t)b*NLIN + 1024;
    for (int n=tid; n<NH; n+=256){
        float iv = sigm(L[n]);
        float fv = sigm(L[1024+n]);
        float gv = tanhf(L[2048+n]);
        float ov = sigm(L[3072+n]);
        float c = fv*g_c[b*NH+n] + iv*gv;
        float h = ov*tanhf(c);
        g_c[b*NH+n] = c;
        g_h[b*NH+n] = h;
        g_hallT[(size_t)n*NM + t*NB + b] = h;   // transposed store [H][t*64+b]
    }
    __syncthreads();
    for (int i=tid; i<NLIN; i+=256) g_lin[b*NLIN + i] = g_biascat[i];
}

// ---------------- launch ----------------
extern "C" void kernel_launch(void* const* d_in, const int* in_sizes, int n_in,
                              void* d_out, int out_size) {
    // order: encoder_out, captions, [lengths], W_enc_att, b_enc_att, W_dec_att,
    // b_dec_att, W_full_att, b_full_att, emb_table, W_ih, b_ih, W_hh, b_hh,
    // W_init_h, b_init_h, W_init_c, b_init_c, W_fbeta, b_fbeta, W_fc, b_fc
    int o = (n_in >= 22 && in_sizes[2] == 1) ? 1 : 0;
    const float* enc      = (const float*)d_in[0];
    const int*   cap      = (const int*)  d_in[1];
    const float* W_enc    = (const float*)d_in[2+o];
    const float* b_enc    = (const float*)d_in[3+o];
    const float* W_dec    = (const float*)d_in[4+o];
    const float* b_dec    = (const float*)d_in[5+o];
    const float* W_full   = (const float*)d_in[6+o];
    const float* b_full   = (const float*)d_in[7+o];
    const float* emb      = (const float*)d_in[8+o];
    const float* W_ih     = (const float*)d_in[9+o];
    const float* b_ih     = (const float*)d_in[10+o];
    const float* W_hh     = (const float*)d_in[11+o];
    const float* b_hh     = (const float*)d_in[12+o];
    const float* W_init_h = (const float*)d_in[13+o];
    const float* b_init_h = (const float*)d_in[14+o];
    const float* W_init_c = (const float*)d_in[15+o];
    const float* b_init_c = (const float*)d_in[16+o];
    const float* W_fbeta  = (const float*)d_in[17+o];
    const float* b_fbeta  = (const float*)d_in[18+o];
    const float* W_fc     = (const float*)d_in[19+o];
    const float* b_fc     = (const float*)d_in[20+o];

    float* preds = (float*)d_out;
    float* aout  = (out_size >= PRED_SIZE + ALPHA_SIZE) ? (preds + PRED_SIZE) : nullptr;

    float *p_att_enc=nullptr, *p_hallT=nullptr, *p_encT=nullptr;
    cudaGetSymbolAddress((void**)&p_att_enc, g_att_enc);
    cudaGetSymbolAddress((void**)&p_hallT,   g_hallT);
    cudaGetSymbolAddress((void**)&p_encT,    g_encT);

    // Setup — ordered so launch index 3 (the slot ncu captured in R8)
    // is the att_enc gemm_tiled, giving a hot-kernel profile next round.
    biascat_kernel<<<20,256>>>(b_dec, b_fbeta, b_ih, b_hh);                    // 0
    mean_kernel<<<dim3(NB,4),128>>>(enc);                                      // 1
    transpose_kernel<<<dim3(NENC/32, NB*NP/32),256>>>(enc, p_encT,
                                                      NB*NP, NENC);            // 2
    // att_enc = encoder_out @ W_enc_att + b_enc_att  (12544 x 512 x 512)
    gemm_tiled<<<dim3(4,98),256>>>(p_encT, W_enc, b_enc, p_att_enc,
                                   NB*NP, NA, NENC, 0);                        // 3 <- ncu
    lin_init_kernel<<<NB,256>>>();                                             // 4
    init_hc_kernel<<<dim3(NB,4),256>>>(b_init_h, b_init_c);                    // 5
    emb_gather_kernel<<<NT*NB,256>>>(emb, cap);                                // 6
    gemm_rec<<<dim3(8,2),256>>>(W_init_h, W_init_c, nullptr, 2, 0);            // 7

    // Recurrence: 4 launches/step
    for (int t=0; t<NT; t++){
        gemm_rec<<<dim3(40,4),256>>>(W_dec, W_fbeta, W_hh, 0, t);
        att_fused_kernel<<<NB,256>>>(enc, W_full, b_full, aout, t);
        gemm_rec<<<dim3(32,6),256>>>(W_ih, nullptr, nullptr, 1, t);
        lstm_kernel<<<NB,256>>>(t);
    }

    // Final logits GEMM: hallT^T(1536x1024) @ W_fc(1024x20000) + b_fc
    gemm_tiled<<<dim3(157,12),256>>>(p_hallT, W_fc, b_fc, preds,
                                     NM, NV, NH, 1);
}

// round 12
// speedup vs baseline: 1.4283x; 1.3900x over previous
#include <cuda_runtime.h>
#include <cuda_bf16.h>
#include <math.h>

#define NB   64
#define NP   196
#define NENC 512
#define NE   1024
#define NH   1024
#define NA   512
#define NV   20000
#define NT   24
#define NCAP 25
#define NLIN 5120          // [attdec 512 | gatepre 512 | gates 4096]
#define NM   (NT*NB)       /* 1536 */
#define NCTA 148
#define PRED_SIZE (NB*NT*NV)   /* 30,720,000 */
#define ALPHA_SIZE (NB*NT*NP)  /* 301,056 */

typedef unsigned long long u64;

// ---------------- device scratch (static; no allocations) ----------------
__device__ float g_att_enc[NB*NP*NA];     // 25.7 MB
__device__ float g_encT[NENC*NB*NP];      // 25.7 MB
__device__ float g_mean[NB*NENC];
__device__ float g_hT[NH*NB];             // h transposed [H][B]
__device__ float g_c[NB*NH];
__device__ float g_hallT[NH*NM];          // [H][t*64+b]
__device__ float g_lin[NB*NLIN];          // bias-preloaded accumulator
__device__ float g_ctxT[NENC*NB];         // gate*context transposed [ENC][B]
__device__ float g_embT[NT*NE*NB];        // embeddings transposed [t][E][B]
__device__ float g_biascat[NLIN];
__device__ unsigned g_bar;                // global barrier counter

// ---------------- helpers ----------------
__device__ __forceinline__ u64 pk2(float lo, float hi){
    u64 r; asm("mov.b64 %0,{%1,%2};" : "=l"(r) : "f"(lo), "f"(hi)); return r;
}
__device__ __forceinline__ void fma2(u64 &d, u64 a, u64 b){
    asm("fma.rn.f32x2 %0,%1,%2,%0;" : "+l"(d) : "l"(a), "l"(b));
}
__device__ __forceinline__ float2 up2(u64 v){
    float2 f; asm("mov.b64 {%0,%1},%2;" : "=f"(f.x), "=f"(f.y) : "l"(v)); return f;
}
__device__ __forceinline__ float sigm(float x){ return 1.0f/(1.0f+expf(-x)); }
__device__ __forceinline__ unsigned su(const void* p){
    return (unsigned)__cvta_generic_to_shared(p);
}
__device__ __forceinline__ void cp16(unsigned saddr, const void* g){
    asm volatile("cp.async.cg.shared.global [%0],[%1],16;" :: "r"(saddr), "l"(g));
}
__device__ __forceinline__ void cp16p(unsigned saddr, const void* g, int bytes){
    asm volatile("cp.async.cg.shared.global [%0],[%1],16,%2;" :: "r"(saddr), "l"(g), "r"(bytes));
}
__device__ __forceinline__ void cp_commit(){ asm volatile("cp.async.commit_group;"); }
__device__ __forceinline__ void cp_wait1(){ asm volatile("cp.async.wait_group 1;" ::: "memory"); }

// global barrier: monotonic counter; tgt advances by NCTA per call.
__device__ __forceinline__ void gbar(unsigned &tgt){
    __syncthreads();
    __threadfence();                       // drain my writes (gpu scope)
    if (threadIdx.x == 0){
        atomicAdd(&g_bar, 1u);
        while (atomicAdd(&g_bar, 0u) < tgt) __nanosleep(128);
    }
    __syncthreads();
    __threadfence();                       // invalidate L1 before fresh reads
    tgt += NCTA;
}

// =====================================================================
// gemm_tiled: C = AT^T @ W + bias, transposed A.
// BM=BN=128, BK=16, 256 threads, 8x8 per thread, f32x2 accumulation.
// cmode 0: plain row-major store.  cmode 1: logits scatter.
// =====================================================================
__global__ void __launch_bounds__(256,2) gemm_tiled(
    const float* __restrict__ AT, const float* __restrict__ W,
    const float* __restrict__ bias, float* __restrict__ C,
    int M, int N, int K, int cmode)
{
    __shared__ __align__(16) float AsT[2][16][128];
    __shared__ __align__(16) float Bs[2][16][128];
    const int bm = blockIdx.y*128, bn = blockIdx.x*128;
    const int tid = threadIdx.x;
    const int ty = tid>>4, tx = tid&15;

    u64 acc[8][4];
    #pragma unroll
    for (int i=0;i<8;i++)
        #pragma unroll
        for (int j=0;j<4;j++) acc[i][j]=0ULL;

    const int KT = K>>4;

    auto load_stage = [&](int kt, int buf){
        int k0 = kt<<4;
        #pragma unroll
        for (int rep=0;rep<2;rep++){
            int i = tid + rep*256;
            int r = i>>5, c4 = i&31;
            cp16(su(&AsT[buf][r][c4*4]), &AT[(size_t)(k0+r)*M + bm + c4*4]);
        }
        #pragma unroll
        for (int rep=0;rep<2;rep++){
            int i = tid + rep*256;
            int r = i>>5, c4 = i&31;
            int gcol = bn + c4*4;
            int inb  = (gcol < N);
            size_t gi = (size_t)(k0+r)*N + (inb ? gcol : 0);
            cp16p(su(&Bs[buf][r][c4*4]), &W[gi], inb ? 16 : 0);
        }
    };

    load_stage(0, 0); cp_commit();

    for (int kt=0; kt<KT; kt++){
        if (kt+1 < KT) load_stage(kt+1, (kt+1)&1);
        cp_commit();
        cp_wait1();
        __syncthreads();
        const int buf = kt&1;
        #pragma unroll
        for (int kk=0;kk<16;kk++){
            u64 a2[8], b2[4];
            {
                float4 a0 = *(const float4*)&AsT[buf][kk][ty*8];
                float4 a1 = *(const float4*)&AsT[buf][kk][ty*8+4];
                a2[0]=pk2(a0.x,a0.x); a2[1]=pk2(a0.y,a0.y);
                a2[2]=pk2(a0.z,a0.z); a2[3]=pk2(a0.w,a0.w);
                a2[4]=pk2(a1.x,a1.x); a2[5]=pk2(a1.y,a1.y);
                a2[6]=pk2(a1.z,a1.z); a2[7]=pk2(a1.w,a1.w);
            }
            #pragma unroll
            for (int u=0;u<2;u++){
                ulonglong2 t = *(const ulonglong2*)&Bs[buf][kk][tx*8 + u*4];
                b2[u*2]=t.x; b2[u*2+1]=t.y;
            }
            #pragma unroll
            for (int i=0;i<8;i++)
                #pragma unroll
                for (int j=0;j<4;j++) fma2(acc[i][j], a2[i], b2[j]);
        }
        __syncthreads();
    }

    #pragma unroll
    for (int i=0;i<8;i++){
        int m = bm + ty*8 + i;
        #pragma unroll
        for (int j=0;j<4;j++){
            int n0 = bn + tx*8 + j*2;
            if (n0 >= N) continue;
            float2 v = up2(acc[i][j]);
            float o0 = v.x + bias[n0], o1 = v.y + bias[n0+1];
            if (cmode==0){
                C[(size_t)m*N + n0]   = o0;
                C[(size_t)m*N + n0+1] = o1;
            } else {
                int b = m & 63, t = m >> 6;
                size_t base = ((size_t)(b*NT + t))*NV + n0;
                C[base]   = o0;
                C[base+1] = o1;
            }
        }
    }
}

// =====================================================================
// Device GEMM for the recurrence: dst += AT^T[64,K-chunk] @ W-chunk.
// AT is transposed [K][64]; A inner read = 2 broadcast LDS.128.
// 256 threads; 8 rows x 4 cols per thread; KT k-tiles of 16.
// =====================================================================
__device__ __forceinline__ void dev_gemm64(
    float* sm, const float* __restrict__ AT, int ak0,
    const float* __restrict__ W, int ldw, int wk0, int wcol,
    float* __restrict__ dst, int ldd, int dcol, int KT)
{
    float (*As)[16][64]  = (float(*)[16][64])sm;            // 2*16*64  = 8KB
    float (*Bs)[16][128] = (float(*)[16][128])(sm + 2048);  // 2*16*128 = 16KB
    const int tid = threadIdx.x;
    const int ty = tid>>5, tx = tid&31;

    u64 acc[8][2];
    #pragma unroll
    for (int i=0;i<8;i++){ acc[i][0]=0ULL; acc[i][1]=0ULL; }

    auto load = [&](int kt, int buf){
        int k = kt<<4;
        {   // A: 16 rows x 64 = 256 float4, 1/thread
            int r = tid>>4, q = tid&15;
            cp16(su(&As[buf][r][q*4]), &AT[(size_t)(ak0+k+r)*64 + q*4]);
        }
        #pragma unroll
        for (int rep=0;rep<2;rep++){
            int i = tid + rep*256;
            int r = i>>5, c4 = i&31;
            cp16(su(&Bs[buf][r][c4*4]), &W[(size_t)(wk0+k+r)*ldw + wcol + c4*4]);
        }
    };

    load(0,0); cp_commit();
    for (int kt=0; kt<KT; kt++){
        if (kt+1 < KT) load(kt+1, (kt+1)&1);
        cp_commit();
        cp_wait1();
        __syncthreads();
        const int buf = kt&1;
        #pragma unroll
        for (int kk=0;kk<16;kk++){
            float4 a0 = *(const float4*)&As[buf][kk][ty*8];
            float4 a1 = *(const float4*)&As[buf][kk][ty*8+4];
            u64 a2[8];
            a2[0]=pk2(a0.x,a0.x); a2[1]=pk2(a0.y,a0.y);
            a2[2]=pk2(a0.z,a0.z); a2[3]=pk2(a0.w,a0.w);
            a2[4]=pk2(a1.x,a1.x); a2[5]=pk2(a1.y,a1.y);
            a2[6]=pk2(a1.z,a1.z); a2[7]=pk2(a1.w,a1.w);
            ulonglong2 bt = *(const ulonglong2*)&Bs[buf][kk][tx*4];
            #pragma unroll
            for (int i=0;i<8;i++){ fma2(acc[i][0], a2[i], bt.x); fma2(acc[i][1], a2[i], bt.y); }
        }
        __syncthreads();
    }

    #pragma unroll
    for (int i=0;i<8;i++){
        int m = ty*8 + i;
        float* dp = dst + (size_t)m*ldd + dcol + tx*4;
        float2 v0 = up2(acc[i][0]), v1 = up2(acc[i][1]);
        atomicAdd((float4*)dp, make_float4(v0.x, v0.y, v1.x, v1.y));
    }
}

// ---------------- att phase body (one CTA per b) ----------------
__device__ void att_body(float* sm, const float* __restrict__ enc,
                         const float* __restrict__ Wfull,
                         const float* __restrict__ bfull,
                         float* __restrict__ aout, int t, int b)
{
    float* s_ad = sm;          // 512
    float* s_w  = sm + 512;    // 512
    float* s_en = sm + 1024;   // 196 (pad to 208)
    float* s_al = sm + 1232;   // 196
    float* red  = sm + 1440;   // 8
    float* s_ms = sm + 1448;   // [0]=max, [1]=sum
    int tid = threadIdx.x, warp = tid>>5, lane = tid&31;

    for (int i=tid; i<NA; i+=256){
        s_ad[i] = g_lin[b*NLIN + i];
        s_w[i]  = Wfull[i];
    }
    __syncthreads();

    float bf = bfull[0];
    for (int p=warp; p<NP; p+=8){
        const float* ae = g_att_enc + (size_t)(b*NP + p)*NA;
        float s = 0.f;
        #pragma unroll
        for (int u=0; u<16; u++){
            int a = lane + u*32;
            s += fmaxf(ae[a] + s_ad[a], 0.f) * s_w[a];
        }
        #pragma unroll
        for (int o=16;o;o>>=1) s += __shfl_xor_sync(0xffffffffu, s, o);
        if (!lane) s_en[p] = s + bf;
    }
    __syncthreads();

    float v = (tid<NP) ? s_en[tid] : -3.4e38f;
    float m = v;
    #pragma unroll
    for (int o=16;o;o>>=1) m = fmaxf(m, __shfl_xor_sync(0xffffffffu, m, o));
    if (!lane) red[warp] = m;
    __syncthreads();
    if (tid==0){
        float mm = red[0];
        #pragma unroll
        for (int i=1;i<8;i++) mm = fmaxf(mm, red[i]);
        s_ms[0] = mm;
    }
    __syncthreads();
    float e = (tid<NP) ? expf(v - s_ms[0]) : 0.f;
    float s = e;
    #pragma unroll
    for (int o=16;o;o>>=1) s += __shfl_xor_sync(0xffffffffu, s, o);
    if (!lane) red[warp] = s;
    __syncthreads();
    if (tid==0){
        float ss = 0.f;
        #pragma unroll
        for (int i=0;i<8;i++) ss += red[i];
        s_ms[1] = ss;
    }
    __syncthreads();
    float inv = 1.0f/s_ms[1];
    if (tid < NP){
        float a = e*inv;
        s_al[tid] = a;
        if (aout) aout[((size_t)b*NT + t)*NP + tid] = a;
    }
    __syncthreads();

    int e0 = tid*2;
    const float* pbase = enc + (size_t)b*NP*NENC + e0;
    float c0=0.f, c1=0.f;
    #pragma unroll 4
    for (int p=0;p<NP;p++){
        float2 w = *(const float2*)(pbase + (size_t)p*NENC);
        float al = s_al[p];
        c0 += al*w.x; c1 += al*w.y;
    }
    float g0 = sigm(g_lin[b*NLIN + 512 + e0]);
    float g1 = sigm(g_lin[b*NLIN + 512 + e0 + 1]);
    g_ctxT[(size_t)e0*64 + b]     = g0*c0;
    g_ctxT[(size_t)(e0+1)*64 + b] = g1*c1;
}

// ---------------- lstm phase body (one CTA per b) ----------------
__device__ void lstm_body(int b, int t){
    int tid = threadIdx.x;
    const float* L = g_lin + (size_t)b*NLIN + 1024;
    for (int n=tid; n<NH; n+=256){
        float iv = sigm(L[n]);
        float fv = sigm(L[1024+n]);
        float gv = tanhf(L[2048+n]);
        float ov = sigm(L[3072+n]);
        float c = fv*g_c[b*NH+n] + iv*gv;
        float h = ov*tanhf(c);
        g_c[b*NH+n] = c;
        g_hT[(size_t)n*64 + b] = h;
        g_hallT[(size_t)n*NM + t*NB + b] = h;
    }
    __syncthreads();
    for (int i=tid; i<NLIN; i+=256) g_lin[b*NLIN + i] = g_biascat[i];
}

// =====================================================================
// Persistent recurrence kernel: 24 steps, 4 phases/step, global barriers.
// grid = 148 CTAs x 256 threads (1/SM, co-resident).
// =====================================================================
__global__ void __launch_bounds__(256) loop_kernel(
    const float* __restrict__ enc,
    const float* __restrict__ W_dec, const float* __restrict__ W_fbeta,
    const float* __restrict__ W_hh,  const float* __restrict__ W_full,
    const float* __restrict__ b_full,const float* __restrict__ W_ih,
    float* __restrict__ aout)
{
    __shared__ __align__(16) float sm[6144];   // 24KB: gemm As+Bs / att scratch
    const int bid = blockIdx.x;
    unsigned tgt = NCTA;

    for (int t=0; t<NT; t++){
        // phase 1: h @ [W_dec | W_fbeta | W_hh]  (320 units: 40 coltiles x 8 kz)
        for (int u = bid; u < 320; u += NCTA){
            int nt = u % 40, kz = u / 40;
            int nc = nt*128;
            const float* W; int wcol, ldw;
            if (nc < 512)       { W=W_dec;   wcol=nc;      ldw=512;  }
            else if (nc < 1024) { W=W_fbeta; wcol=nc-512;  ldw=512;  }
            else                { W=W_hh;    wcol=nc-1024; ldw=4096; }
            dev_gemm64(sm, g_hT, kz*128, W, ldw, kz*128, wcol,
                       g_lin, NLIN, nc, 8);
        }
        gbar(tgt);

        // phase 2: att (CTAs 0..63)  ||  emb-half of x@W_ih (CTAs 64..147)
        if (bid < 64){
            att_body(sm, enc, W_full, b_full, aout, t, bid);
        } else {
            for (int u = bid-64; u < 128; u += (NCTA-64)){
                int nt = u & 31, kz = u >> 5;        // kz 0..3 over K=1024
                dev_gemm64(sm, g_embT + (size_t)t*NE*64, kz*256,
                           W_ih, 4096, kz*256, nt*128,
                           g_lin, NLIN, 1024 + nt*128, 16);
            }
        }
        gbar(tgt);

        // phase 3: ctx-half of x@W_ih (128 units: 32 coltiles x 4 kz over K=512)
        if (bid < 128){
            int nt = bid & 31, kz = bid >> 5;
            dev_gemm64(sm, g_ctxT, kz*128,
                       W_ih, 4096, 1024 + kz*128, nt*128,
                       g_lin, NLIN, 1024 + nt*128, 8);
        }
        gbar(tgt);

        // phase 4: lstm + g_lin reset
        if (bid < 64) lstm_body(bid, t);
        gbar(tgt);
    }
}

// ---------------- setup kernels ----------------
__global__ void biascat_kernel(const float* __restrict__ b_dec, const float* __restrict__ b_fb,
                               const float* __restrict__ b_ih, const float* __restrict__ b_hh){
    int i = blockIdx.x*256 + threadIdx.x;
    if (blockIdx.x==0 && threadIdx.x==0) g_bar = 0u;   // barrier reset per replay
    if (i < 512)       g_biascat[i] = b_dec[i];
    else if (i < 1024) g_biascat[i] = b_fb[i-512];
    else if (i < NLIN) g_biascat[i] = b_ih[i-1024] + b_hh[i-1024];
}

__global__ void lin_init_kernel(){
    int b = blockIdx.x;
    for (int i=threadIdx.x; i<NLIN; i+=256) g_lin[b*NLIN + i] = g_biascat[i];
}

__global__ void mean_kernel(const float* __restrict__ enc){
    int b = blockIdx.x;
    int e = blockIdx.y*128 + threadIdx.x;
    const float* p = enc + (size_t)b*NP*NENC + e;
    float s = 0.f;
    #pragma unroll 4
    for (int i=0;i<NP;i++) s += p[(size_t)i*NENC];
    g_mean[b*NENC + e] = s * (1.0f/(float)NP);
}

__global__ void init_hc_kernel(const float* __restrict__ bh, const float* __restrict__ bc){
    int b = blockIdx.x;
    int n = blockIdx.y*256 + threadIdx.x;
    g_hT[(size_t)n*64 + b] = bh[n];
    g_c[b*NH + n] = bc[n];
}

// h0/c0 = mean @ W_init_{h,c}; grid(8,2).  kz=0 -> g_hT (transposed), kz=1 -> g_c.
__global__ void __launch_bounds__(256) init_gemm(
    const float* __restrict__ W0, const float* __restrict__ W1)
{
    __shared__ __align__(16) float As[2][64][16];
    __shared__ __align__(16) float Bs[2][16][128];
    const int nt = blockIdx.x, kz = blockIdx.y;
    const int tid = threadIdx.x;
    const float* Wp = (kz==0) ? W0 : W1;
    const int wcol = nt*128;

    const int ty = tid>>5, tx = tid&31;
    u64 acc[8][2];
    #pragma unroll
    for (int i=0;i<8;i++){ acc[i][0]=0ULL; acc[i][1]=0ULL; }

    auto load = [&](int kt, int buf){
        int k = kt<<4;
        {
            int r = tid>>2, q = tid&3;
            cp16(su(&As[buf][r][q*4]), &g_mean[(size_t)r*NENC + k + q*4]);
        }
        #pragma unroll
        for (int rep=0;rep<2;rep++){
            int i = tid + rep*256;
            int r = i>>5, c4 = i&31;
            cp16(su(&Bs[buf][r][c4*4]), &Wp[(size_t)(k+r)*NH + wcol + c4*4]);
        }
    };

    load(0,0); cp_commit();
    const int KT = NENC/16;
    for (int kt=0; kt<KT; kt++){
        if (kt+1 < KT) load(kt+1, (kt+1)&1);
        cp_commit(); cp_wait1(); __syncthreads();
        const int buf = kt&1;
        #pragma unroll
        for (int kk=0;kk<16;kk++){
            u64 a2[8];
            #pragma unroll
            for (int i=0;i<8;i++){
                float av = As[buf][ty*8 + i][kk];
                a2[i] = pk2(av, av);
            }
            ulonglong2 bt = *(const ulonglong2*)&Bs[buf][kk][tx*4];
            #pragma unroll
            for (int i=0;i<8;i++){ fma2(acc[i][0], a2[i], bt.x); fma2(acc[i][1], a2[i], bt.y); }
        }
        __syncthreads();
    }

    #pragma unroll
    for (int i=0;i<8;i++){
        int m = ty*8 + i;
        float2 v0 = up2(acc[i][0]), v1 = up2(acc[i][1]);
        float vv[4] = {v0.x, v0.y, v1.x, v1.y};
        if (kz == 0){
            #pragma unroll
            for (int j=0;j<4;j++)
                atomicAdd(&g_hT[(size_t)(wcol + tx*4 + j)*64 + m], vv[j]);
        } else {
            atomicAdd((float4*)&g_c[(size_t)m*NH + wcol + tx*4],
                      make_float4(vv[0], vv[1], vv[2], vv[3]));
        }
    }
}

// Tiled transpose: out[C][R] = in[R][C].  R,C multiples of 32.
__global__ void transpose_kernel(const float* __restrict__ in, float* __restrict__ out,
                                 int R, int C){
    __shared__ float tile[32][33];
    int cb = blockIdx.x*32, rb = blockIdx.y*32;
    int tx = threadIdx.x&31, ty = threadIdx.x>>5;
    #pragma unroll
    for (int j=0;j<32;j+=8)
        tile[ty+j][tx] = in[(size_t)(rb+ty+j)*C + cb+tx];
    __syncthreads();
    #pragma unroll
    for (int j=0;j<32;j+=8)
        out[(size_t)(cb+ty+j)*R + rb+tx] = tile[tx][ty+j];
}

__global__ void emb_gatherT_kernel(const float* __restrict__ emb, const int* __restrict__ cap){
    int tb = blockIdx.x;                 // t*64 + b
    int t = tb>>6, b = tb&63;
    int tok = cap[b*NCAP + t];
    const float* src = emb + (size_t)tok*NE;
    float* dst = g_embT + (size_t)t*NE*64;
    for (int e=threadIdx.x; e<NE; e+=256)
        dst[(size_t)e*64 + b] = src[e];
}

// ---------------- launch ----------------
extern "C" void kernel_launch(void* const* d_in, const int* in_sizes, int n_in,
                              void* d_out, int out_size) {
    int o = (n_in >= 22 && in_sizes[2] == 1) ? 1 : 0;
    const float* enc      = (const float*)d_in[0];
    const int*   cap      = (const int*)  d_in[1];
    const float* W_enc    = (const float*)d_in[2+o];
    const float* b_enc    = (const float*)d_in[3+o];
    const float* W_dec    = (const float*)d_in[4+o];
    const float* b_dec    = (const float*)d_in[5+o];
    const float* W_full   = (const float*)d_in[6+o];
    const float* b_full   = (const float*)d_in[7+o];
    const float* emb      = (const float*)d_in[8+o];
    const float* W_ih     = (const float*)d_in[9+o];
    const float* b_ih     = (const float*)d_in[10+o];
    const float* W_hh     = (const float*)d_in[11+o];
    const float* b_hh     = (const float*)d_in[12+o];
    const float* W_init_h = (const float*)d_in[13+o];
    const float* b_init_h = (const float*)d_in[14+o];
    const float* W_init_c = (const float*)d_in[15+o];
    const float* b_init_c = (const float*)d_in[16+o];
    const float* W_fbeta  = (const float*)d_in[17+o];
    const float* b_fbeta  = (const float*)d_in[18+o];
    const float* W_fc     = (const float*)d_in[19+o];
    const float* b_fc     = (const float*)d_in[20+o];

    float* preds = (float*)d_out;
    float* aout  = (out_size >= PRED_SIZE + ALPHA_SIZE) ? (preds + PRED_SIZE) : nullptr;

    float *p_att_enc=nullptr, *p_hallT=nullptr, *p_encT=nullptr;
    cudaGetSymbolAddress((void**)&p_att_enc, g_att_enc);
    cudaGetSymbolAddress((void**)&p_hallT,   g_hallT);
    cudaGetSymbolAddress((void**)&p_encT,    g_encT);

    // Setup
    biascat_kernel<<<20,256>>>(b_dec, b_fbeta, b_ih, b_hh);
    mean_kernel<<<dim3(NB,4),128>>>(enc);
    transpose_kernel<<<dim3(NENC/32, NB*NP/32),256>>>(enc, p_encT, NB*NP, NENC);
    gemm_tiled<<<dim3(4,98),256>>>(p_encT, W_enc, b_enc, p_att_enc,
                                   NB*NP, NA, NENC, 0);
    lin_init_kernel<<<NB,256>>>();
    init_hc_kernel<<<dim3(NB,4),256>>>(b_init_h, b_init_c);
    emb_gatherT_kernel<<<NT*NB,256>>>(emb, cap);
    init_gemm<<<dim3(8,2),256>>>(W_init_h, W_init_c);

    // Whole recurrence in ONE persistent kernel
    loop_kernel<<<NCTA,256>>>(enc, W_dec, W_fbeta, W_hh, W_full, b_full,
                              W_ih, aout);

    // Final logits GEMM: hallT^T(1536x1024) @ W_fc(1024x20000) + b_fc
    gemm_tiled<<<dim3(157,12),256>>>(p_hallT, W_fc, b_fc, preds,
                                     NM, NV, NH, 1);
}

// round 15
// speedup vs baseline: 1.7043x; 1.1932x over previous
#include <cuda_runtime.h>
#include <cuda_bf16.h>
#include <stdint.h>
#include <math.h>

#define NB   64
#define NP   196
#define NENC 512
#define NE   1024
#define NH   1024
#define NA   512
#define NV   20000
#define NVP  20096         /* NV padded to 157*128 */
#define NT   24
#define NCAP 25
#define NLIN 5120
#define NM   (NT*NB)       /* 1536 */
#define NCTA 148
#define PRED_SIZE (NB*NT*NV)
#define ALPHA_SIZE (NB*NT*NP)

typedef unsigned long long u64;

// ---------------- device scratch (static; no allocations) ----------------
__device__ float g_att_enc[NB*NP*NA];
__device__ float g_encT[NENC*NB*NP];
__device__ float g_mean[NB*NENC];
__device__ float g_hT[NH*NB];
__device__ float g_c[NB*NH];
__device__ float g_hall[NM*NH];           // row-major [m][K], m = t*64+b
__device__ float g_lin[NB*NLIN];
__device__ float g_ctxT[NENC*NB];
__device__ float g_embT[NT*NE*NB];
__device__ float g_biascat[NLIN];
__device__ unsigned g_bar;
// bf16 split planes for tensor-core logits GEMM
__device__ __nv_bfloat16 g_Ahi[NM*NH];    // 3 MB
__device__ __nv_bfloat16 g_Alo[NM*NH];
__device__ __nv_bfloat16 g_Whi[(size_t)NVP*NH];  // 41 MB, [n][k]
__device__ __nv_bfloat16 g_Wlo[(size_t)NVP*NH];

// ---------------- helpers ----------------
__device__ __forceinline__ u64 pk2(float lo, float hi){
    u64 r; asm("mov.b64 %0,{%1,%2};" : "=l"(r) : "f"(lo), "f"(hi)); return r;
}
__device__ __forceinline__ void fma2(u64 &d, u64 a, u64 b){
    asm("fma.rn.f32x2 %0,%1,%2,%0;" : "+l"(d) : "l"(a), "l"(b));
}
__device__ __forceinline__ float2 up2(u64 v){
    float2 f; asm("mov.b64 {%0,%1},%2;" : "=f"(f.x), "=f"(f.y) : "l"(v)); return f;
}
__device__ __forceinline__ float sigm(float x){ return 1.0f/(1.0f+expf(-x)); }
__device__ __forceinline__ unsigned su(const void* p){
    return (unsigned)__cvta_generic_to_shared(p);
}
__device__ __forceinline__ void cp16(unsigned saddr, const void* g){
    asm volatile("cp.async.cg.shared.global [%0],[%1],16;" :: "r"(saddr), "l"(g));
}
__device__ __forceinline__ void cp16p(unsigned saddr, const void* g, int bytes){
    asm volatile("cp.async.cg.shared.global [%0],[%1],16,%2;" :: "r"(saddr), "l"(g), "r"(bytes));
}
__device__ __forceinline__ void cp_commit(){ asm volatile("cp.async.commit_group;"); }
__device__ __forceinline__ void cp_wait1(){ asm volatile("cp.async.wait_group 1;" ::: "memory"); }

// global barrier
__device__ __forceinline__ void gbar(unsigned &tgt){
    __syncthreads();
    __threadfence();
    if (threadIdx.x == 0){
        atomicAdd(&g_bar, 1u);
        while (atomicAdd(&g_bar, 0u) < tgt) __nanosleep(128);
    }
    __syncthreads();
    __threadfence();
    tgt += NCTA;
}

// ---------------- warp-MMA primitives (base ISA, sm_80+) ----------------
__device__ __forceinline__ void ldsm4(uint32_t &r0, uint32_t &r1, uint32_t &r2,
                                      uint32_t &r3, uint32_t addr){
    asm volatile("ldmatrix.sync.aligned.m8n8.x4.shared.b16 {%0,%1,%2,%3}, [%4];"
        : "=r"(r0), "=r"(r1), "=r"(r2), "=r"(r3) : "r"(addr));
}
__device__ __forceinline__ void mma16816(float* d, const uint32_t* a, uint32_t b0, uint32_t b1){
    asm volatile("mma.sync.aligned.m16n8k16.row.col.f32.bf16.bf16.f32 "
        "{%0,%1,%2,%3},{%4,%5,%6,%7},{%8,%9},{%0,%1,%2,%3};"
        : "+f"(d[0]), "+f"(d[1]), "+f"(d[2]), "+f"(d[3])
        : "r"(a[0]), "r"(a[1]), "r"(a[2]), "r"(a[3]), "r"(b0), "r"(b1));
}

// =====================================================================
// gemm_tiled: C = AT^T @ W + bias (fp32, FFMA2) — used for att_enc only.
// =====================================================================
__global__ void __launch_bounds__(256,2) gemm_tiled(
    const float* __restrict__ AT, const float* __restrict__ W,
    const float* __restrict__ bias, float* __restrict__ C,
    int M, int N, int K)
{
    __shared__ __align__(16) float AsT[2][16][128];
    __shared__ __align__(16) float Bs[2][16][128];
    const int bm = blockIdx.y*128, bn = blockIdx.x*128;
    const int tid = threadIdx.x;
    const int ty = tid>>4, tx = tid&15;

    u64 acc[8][4];
    #pragma unroll
    for (int i=0;i<8;i++)
        #pragma unroll
        for (int j=0;j<4;j++) acc[i][j]=0ULL;

    const int KT = K>>4;

    auto load_stage = [&](int kt, int buf){
        int k0 = kt<<4;
        #pragma unroll
        for (int rep=0;rep<2;rep++){
            int i = tid + rep*256;
            int r = i>>5, c4 = i&31;
            cp16(su(&AsT[buf][r][c4*4]), &AT[(size_t)(k0+r)*M + bm + c4*4]);
        }
        #pragma unroll
        for (int rep=0;rep<2;rep++){
            int i = tid + rep*256;
            int r = i>>5, c4 = i&31;
            int gcol = bn + c4*4;
            int inb  = (gcol < N);
            size_t gi = (size_t)(k0+r)*N + (inb ? gcol : 0);
            cp16p(su(&Bs[buf][r][c4*4]), &W[gi], inb ? 16 : 0);
        }
    };

    load_stage(0, 0); cp_commit();

    for (int kt=0; kt<KT; kt++){
        if (kt+1 < KT) load_stage(kt+1, (kt+1)&1);
        cp_commit();
        cp_wait1();
        __syncthreads();
        const int buf = kt&1;
        #pragma unroll
        for (int kk=0;kk<16;kk++){
            u64 a2[8], b2[4];
            {
                float4 a0 = *(const float4*)&AsT[buf][kk][ty*8];
                float4 a1 = *(const float4*)&AsT[buf][kk][ty*8+4];
                a2[0]=pk2(a0.x,a0.x); a2[1]=pk2(a0.y,a0.y);
                a2[2]=pk2(a0.z,a0.z); a2[3]=pk2(a0.w,a0.w);
                a2[4]=pk2(a1.x,a1.x); a2[5]=pk2(a1.y,a1.y);
                a2[6]=pk2(a1.z,a1.z); a2[7]=pk2(a1.w,a1.w);
            }
            #pragma unroll
            for (int u=0;u<2;u++){
                ulonglong2 t = *(const ulonglong2*)&Bs[buf][kk][tx*8 + u*4];
                b2[u*2]=t.x; b2[u*2+1]=t.y;
            }
            #pragma unroll
            for (int i=0;i<8;i++)
                #pragma unroll
                for (int j=0;j<4;j++) fma2(acc[i][j], a2[i], b2[j]);
        }
        __syncthreads();
    }

    #pragma unroll
    for (int i=0;i<8;i++){
        int m = bm + ty*8 + i;
        #pragma unroll
        for (int j=0;j<4;j++){
            int n0 = bn + tx*8 + j*2;
            if (n0 >= N) continue;
            float2 v = up2(acc[i][j]);
            C[(size_t)m*N + n0]   = v.x + bias[n0];
            C[(size_t)m*N + n0+1] = v.y + bias[n0+1];
        }
    }
}

// =====================================================================
// Logits GEMM via mma.sync bf16 split (hi*hi + hi*lo + lo*hi).
// Tile 128x128; 8 warps, each 64x32; K=1024 in 32-wide chunks,
// 2-stage cp.async. SMEM planes have 80B row stride (ldmatrix
// conflict-free: banks r*20 mod 32 all distinct).
// grid(157,12), 256 threads, 80KB dynamic smem.
// Output scatter: row m=t*64+b -> preds[(b*NT+t)*NV + n], n<NV guard.
// =====================================================================
#define PLANE 10240            /* 128 rows * 80B */
#define STAGE (4*PLANE)        /* Ahi,Alo,Bhi,Blo */

__global__ void __launch_bounds__(256) logits_mma(
    const __nv_bfloat16* __restrict__ Ahi, const __nv_bfloat16* __restrict__ Alo,
    const __nv_bfloat16* __restrict__ Bhi, const __nv_bfloat16* __restrict__ Blo,
    const float* __restrict__ bias, float* __restrict__ preds)
{
    extern __shared__ char dsm[];
    const int tid = threadIdx.x, wid = tid>>5, lane = tid&31;
    const int bm = blockIdx.y*128, bn = blockIdx.x*128;
    const int wm = wid>>2, wn = wid&3;        // warp tile: rows wm*64, cols wn*32
    const uint32_t sbase = su(dsm);

    float acc[4][4][4];
    #pragma unroll
    for (int i=0;i<4;i++)
        #pragma unroll
        for (int j=0;j<4;j++)
            #pragma unroll
            for (int r=0;r<4;r++) acc[i][j][r]=0.f;

    auto ld_stage = [&](int c, int s){
        uint32_t st = sbase + s*STAGE;
        int k0 = c*32;
        #pragma unroll
        for (int it=0; it<8; ++it){
            int idx = tid + it*256;          // 0..2047
            int p = idx >> 9;                // plane
            int rj = idx & 511;
            int r = rj >> 2, j = rj & 3;
            const __nv_bfloat16* src;
            if      (p==0) src = Ahi + (size_t)(bm+r)*NH + k0 + j*8;
            else if (p==1) src = Alo + (size_t)(bm+r)*NH + k0 + j*8;
            else if (p==2) src = Bhi + (size_t)(bn+r)*NH + k0 + j*8;
            else           src = Blo + (size_t)(bn+r)*NH + k0 + j*8;
            cp16(st + p*PLANE + r*80 + j*16, src);
        }
    };

    ld_stage(0,0); cp_commit();

    const int q  = lane>>3, i8 = lane&7;
    const int rq = (q&1)*8 + i8;             // row offset within 16-row tile
    const int kq = (q>>1)*16;                // byte offset within 32B k16

    for (int c=0; c<32; c++){
        if (c+1 < 32) ld_stage(c+1, (c+1)&1);
        cp_commit();
        cp_wait1();
        __syncthreads();
        const uint32_t st = sbase + (c&1)*STAGE;
        const uint32_t aO = st, alO = st+PLANE, bO = st+2*PLANE, blO = st+3*PLANE;

        #pragma unroll
        for (int kh=0; kh<2; kh++){
            uint32_t Ah[4][4], Al[4][4], Bh[2][4], Bl[2][4];
            #pragma unroll
            for (int mt=0; mt<4; mt++){
                uint32_t off = (uint32_t)(wm*64 + mt*16 + rq)*80 + kh*32 + kq;
                ldsm4(Ah[mt][0],Ah[mt][1],Ah[mt][2],Ah[mt][3], aO  + off);
                ldsm4(Al[mt][0],Al[mt][1],Al[mt][2],Al[mt][3], alO + off);
            }
            #pragma unroll
            for (int g=0; g<2; g++){
                uint32_t off = (uint32_t)(wn*32 + g*16 + rq)*80 + kh*32 + kq;
                ldsm4(Bh[g][0],Bh[g][1],Bh[g][2],Bh[g][3], bO  + off);
                ldsm4(Bl[g][0],Bl[g][1],Bl[g][2],Bl[g][3], blO + off);
            }
            #pragma unroll
            for (int mt=0; mt<4; mt++){
                #pragma unroll
                for (int nt=0; nt<4; nt++){
                    int g = nt>>1, sel = nt&1;
                    mma16816(acc[mt][nt], Ah[mt], Bh[g][sel],   Bh[g][2+sel]);
                    mma16816(acc[mt][nt], Ah[mt], Bl[g][sel],   Bl[g][2+sel]);
                    mma16816(acc[mt][nt], Al[mt], Bh[g][sel],   Bh[g][2+sel]);
                }
            }
        }
        __syncthreads();
    }

    // epilogue: scatter with bias
    #pragma unroll
    for (int mt=0; mt<4; mt++){
        #pragma unroll
        for (int nt=0; nt<4; nt++){
            int n0 = bn + wn*32 + nt*8 + (lane&3)*2;
            if (n0 >= NV) continue;
            float b0 = bias[n0], b1 = bias[n0+1];
            int r0 = bm + wm*64 + mt*16 + (lane>>2);
            #pragma unroll
            for (int h=0; h<2; h++){
                int m = r0 + h*8;
                int b = m & 63, t = m >> 6;
                size_t rb = ((size_t)(b*NT + t))*NV + n0;
                float2 o;
                o.x = acc[mt][nt][h*2+0] + b0;
                o.y = acc[mt][nt][h*2+1] + b1;
                *(float2*)&preds[rb] = o;
            }
        }
    }
}

// =====================================================================
// dev_gemm64: recurrence split-K GEMM unit (unchanged)
// =====================================================================
__device__ __forceinline__ void dev_gemm64(
    float* sm, const float* __restrict__ AT, int ak0,
    const float* __restrict__ W, int ldw, int wk0, int wcol,
    float* __restrict__ dst, int ldd, int dcol, int KT)
{
    float (*As)[16][64]  = (float(*)[16][64])sm;
    float (*Bs)[16][128] = (float(*)[16][128])(sm + 2048);
    const int tid = threadIdx.x;
    const int ty = tid>>5, tx = tid&31;

    u64 acc[8][2];
    #pragma unroll
    for (int i=0;i<8;i++){ acc[i][0]=0ULL; acc[i][1]=0ULL; }

    auto load = [&](int kt, int buf){
        int k = kt<<4;
        {
            int r = tid>>4, qq = tid&15;
            cp16(su(&As[buf][r][qq*4]), &AT[(size_t)(ak0+k+r)*64 + qq*4]);
        }
        #pragma unroll
        for (int rep=0;rep<2;rep++){
            int i = tid + rep*256;
            int r = i>>5, c4 = i&31;
            cp16(su(&Bs[buf][r][c4*4]), &W[(size_t)(wk0+k+r)*ldw + wcol + c4*4]);
        }
    };

    load(0,0); cp_commit();
    for (int kt=0; kt<KT; kt++){
        if (kt+1 < KT) load(kt+1, (kt+1)&1);
        cp_commit();
        cp_wait1();
        __syncthreads();
        const int buf = kt&1;
        #pragma unroll
        for (int kk=0;kk<16;kk++){
            float4 a0 = *(const float4*)&As[buf][kk][ty*8];
            float4 a1 = *(const float4*)&As[buf][kk][ty*8+4];
            u64 a2[8];
            a2[0]=pk2(a0.x,a0.x); a2[1]=pk2(a0.y,a0.y);
            a2[2]=pk2(a0.z,a0.z); a2[3]=pk2(a0.w,a0.w);
            a2[4]=pk2(a1.x,a1.x); a2[5]=pk2(a1.y,a1.y);
            a2[6]=pk2(a1.z,a1.z); a2[7]=pk2(a1.w,a1.w);
            ulonglong2 bt = *(const ulonglong2*)&Bs[buf][kk][tx*4];
            #pragma unroll
            for (int i=0;i<8;i++){ fma2(acc[i][0], a2[i], bt.x); fma2(acc[i][1], a2[i], bt.y); }
        }
        __syncthreads();
    }

    #pragma unroll
    for (int i=0;i<8;i++){
        int m = ty*8 + i;
        float* dp = dst + (size_t)m*ldd + dcol + tx*4;
        float2 v0 = up2(acc[i][0]), v1 = up2(acc[i][1]);
        atomicAdd((float4*)dp, make_float4(v0.x, v0.y, v1.x, v1.y));
    }
}

// ---------------- att phase body ----------------
__device__ void att_body(float* sm, const float* __restrict__ enc,
                         const float* __restrict__ Wfull,
                         const float* __restrict__ bfull,
                         float* __restrict__ aout, int t, int b)
{
    float* s_ad = sm;
    float* s_w  = sm + 512;
    float* s_en = sm + 1024;
    float* s_al = sm + 1232;
    float* red  = sm + 1440;
    float* s_ms = sm + 1448;
    int tid = threadIdx.x, warp = tid>>5, lane = tid&31;

    for (int i=tid; i<NA; i+=256){
        s_ad[i] = g_lin[b*NLIN + i];
        s_w[i]  = Wfull[i];
    }
    __syncthreads();

    float bf = bfull[0];
    for (int p=warp; p<NP; p+=8){
        const float* ae = g_att_enc + (size_t)(b*NP + p)*NA;
        float s = 0.f;
        #pragma unroll
        for (int u=0; u<16; u++){
            int a = lane + u*32;
            s += fmaxf(ae[a] + s_ad[a], 0.f) * s_w[a];
        }
        #pragma unroll
        for (int o=16;o;o>>=1) s += __shfl_xor_sync(0xffffffffu, s, o);
        if (!lane) s_en[p] = s + bf;
    }
    __syncthreads();

    float v = (tid<NP) ? s_en[tid] : -3.4e38f;
    float m = v;
    #pragma unroll
    for (int o=16;o;o>>=1) m = fmaxf(m, __shfl_xor_sync(0xffffffffu, m, o));
    if (!lane) red[warp] = m;
    __syncthreads();
    if (tid==0){
        float mm = red[0];
        #pragma unroll
        for (int i=1;i<8;i++) mm = fmaxf(mm, red[i]);
        s_ms[0] = mm;
    }
    __syncthreads();
    float e = (tid<NP) ? expf(v - s_ms[0]) : 0.f;
    float s = e;
    #pragma unroll
    for (int o=16;o;o>>=1) s += __shfl_xor_sync(0xffffffffu, s, o);
    if (!lane) red[warp] = s;
    __syncthreads();
    if (tid==0){
        float ss = 0.f;
        #pragma unroll
        for (int i=0;i<8;i++) ss += red[i];
        s_ms[1] = ss;
    }
    __syncthreads();
    float inv = 1.0f/s_ms[1];
    if (tid < NP){
        float a = e*inv;
        s_al[tid] = a;
        if (aout) aout[((size_t)b*NT + t)*NP + tid] = a;
    }
    __syncthreads();

    int e0 = tid*2;
    const float* pbase = enc + (size_t)b*NP*NENC + e0;
    float c0=0.f, c1=0.f;
    #pragma unroll 4
    for (int p=0;p<NP;p++){
        float2 w = *(const float2*)(pbase + (size_t)p*NENC);
        float al = s_al[p];
        c0 += al*w.x; c1 += al*w.y;
    }
    float g0 = sigm(g_lin[b*NLIN + 512 + e0]);
    float g1 = sigm(g_lin[b*NLIN + 512 + e0 + 1]);
    g_ctxT[(size_t)e0*64 + b]     = g0*c0;
    g_ctxT[(size_t)(e0+1)*64 + b] = g1*c1;
}

// ---------------- lstm phase body ----------------
__device__ void lstm_body(int b, int t){
    int tid = threadIdx.x;
    const float* L = g_lin + (size_t)b*NLIN + 1024;
    for (int n=tid; n<NH; n+=256){
        float iv = sigm(L[n]);
        float fv = sigm(L[1024+n]);
        float gv = tanhf(L[2048+n]);
        float ov = sigm(L[3072+n]);
        float c = fv*g_c[b*NH+n] + iv*gv;
        float h = ov*tanhf(c);
        g_c[b*NH+n] = c;
        g_hT[(size_t)n*64 + b] = h;
        g_hall[((size_t)(t*NB + b))*NH + n] = h;   // row-major for bf16 split
    }
    __syncthreads();
    for (int i=tid; i<NLIN; i+=256) g_lin[b*NLIN + i] = g_biascat[i];
}

// =====================================================================
// Persistent recurrence kernel
// =====================================================================
__global__ void __launch_bounds__(256) loop_kernel(
    const float* __restrict__ enc,
    const float* __restrict__ W_dec, const float* __restrict__ W_fbeta,
    const float* __restrict__ W_hh,  const float* __restrict__ W_full,
    const float* __restrict__ b_full,const float* __restrict__ W_ih,
    float* __restrict__ aout)
{
    __shared__ __align__(16) float sm[6144];
    const int bid = blockIdx.x;
    unsigned tgt = NCTA;

    for (int t=0; t<NT; t++){
        for (int u = bid; u < 320; u += NCTA){
            int nt = u % 40, kz = u / 40;
            int nc = nt*128;
            const float* W; int wcol, ldw;
            if (nc < 512)       { W=W_dec;   wcol=nc;      ldw=512;  }
            else if (nc < 1024) { W=W_fbeta; wcol=nc-512;  ldw=512;  }
            else                { W=W_hh;    wcol=nc-1024; ldw=4096; }
            dev_gemm64(sm, g_hT, kz*128, W, ldw, kz*128, wcol,
                       g_lin, NLIN, nc, 8);
        }
        gbar(tgt);

        if (bid < 64){
            att_body(sm, enc, W_full, b_full, aout, t, bid);
        } else {
            for (int u = bid-64; u < 128; u += (NCTA-64)){
                int nt = u & 31, kz = u >> 5;
                dev_gemm64(sm, g_embT + (size_t)t*NE*64, kz*256,
                           W_ih, 4096, kz*256, nt*128,
                           g_lin, NLIN, 1024 + nt*128, 16);
            }
        }
        gbar(tgt);

        if (bid < 128){
            int nt = bid & 31, kz = bid >> 5;
            dev_gemm64(sm, g_ctxT, kz*128,
                       W_ih, 4096, 1024 + kz*128, nt*128,
                       g_lin, NLIN, 1024 + nt*128, 8);
        }
        gbar(tgt);

        if (bid < 64) lstm_body(bid, t);
        gbar(tgt);
    }
}

// ---------------- setup kernels ----------------
__global__ void biascat_kernel(const float* __restrict__ b_dec, const float* __restrict__ b_fb,
                               const float* __restrict__ b_ih, const float* __restrict__ b_hh){
    int i = blockIdx.x*256 + threadIdx.x;
    if (blockIdx.x==0 && threadIdx.x==0) g_bar = 0u;
    if (i < 512)       g_biascat[i] = b_dec[i];
    else if (i < 1024) g_biascat[i] = b_fb[i-512];
    else if (i < NLIN) g_biascat[i] = b_ih[i-1024] + b_hh[i-1024];
}

__global__ void lin_init_kernel(){
    int b = blockIdx.x;
    for (int i=threadIdx.x; i<NLIN; i+=256) g_lin[b*NLIN + i] = g_biascat[i];
}

__global__ void mean_kernel(const float* __restrict__ enc){
    int b = blockIdx.x;
    int e = blockIdx.y*128 + threadIdx.x;
    const float* p = enc + (size_t)b*NP*NENC + e;
    float s = 0.f;
    #pragma unroll 4
    for (int i=0;i<NP;i++) s += p[(size_t)i*NENC];
    g_mean[b*NENC + e] = s * (1.0f/(float)NP);
}

__global__ void init_hc_kernel(const float* __restrict__ bh, const float* __restrict__ bc){
    int b = blockIdx.x;
    int n = blockIdx.y*256 + threadIdx.x;
    g_hT[(size_t)n*64 + b] = bh[n];
    g_c[b*NH + n] = bc[n];
}

__global__ void __launch_bounds__(256) init_gemm(
    const float* __restrict__ W0, const float* __restrict__ W1)
{
    __shared__ __align__(16) float As[2][64][16];
    __shared__ __align__(16) float Bs[2][16][128];
    const int nt = blockIdx.x, kz = blockIdx.y;
    const int tid = threadIdx.x;
    const float* Wp = (kz==0) ? W0 : W1;
    const int wcol = nt*128;

    const int ty = tid>>5, tx = tid&31;
    u64 acc[8][2];
    #pragma unroll
    for (int i=0;i<8;i++){ acc[i][0]=0ULL; acc[i][1]=0ULL; }

    auto load = [&](int kt, int buf){
        int k = kt<<4;
        {
            int r = tid>>2, qq = tid&3;
            cp16(su(&As[buf][r][qq*4]), &g_mean[(size_t)r*NENC + k + qq*4]);
        }
        #pragma unroll
        for (int rep=0;rep<2;rep++){
            int i = tid + rep*256;
            int r = i>>5, c4 = i&31;
            cp16(su(&Bs[buf][r][c4*4]), &Wp[(size_t)(k+r)*NH + wcol + c4*4]);
        }
    };

    load(0,0); cp_commit();
    const int KT = NENC/16;
    for (int kt=0; kt<KT; kt++){
        if (kt+1 < KT) load(kt+1, (kt+1)&1);
        cp_commit(); cp_wait1(); __syncthreads();
        const int buf = kt&1;
        #pragma unroll
        for (int kk=0;kk<16;kk++){
            u64 a2[8];
            #pragma unroll
            for (int i=0;i<8;i++){
                float av = As[buf][ty*8 + i][kk];
                a2[i] = pk2(av, av);
            }
            ulonglong2 bt = *(const ulonglong2*)&Bs[buf][kk][tx*4];
            #pragma unroll
            for (int i=0;i<8;i++){ fma2(acc[i][0], a2[i], bt.x); fma2(acc[i][1], a2[i], bt.y); }
        }
        __syncthreads();
    }

    #pragma unroll
    for (int i=0;i<8;i++){
        int m = ty*8 + i;
        float2 v0 = up2(acc[i][0]), v1 = up2(acc[i][1]);
        float vv[4] = {v0.x, v0.y, v1.x, v1.y};
        if (kz == 0){
            #pragma unroll
            for (int j=0;j<4;j++)
                atomicAdd(&g_hT[(size_t)(wcol + tx*4 + j)*64 + m], vv[j]);
        } else {
            atomicAdd((float4*)&g_c[(size_t)m*NH + wcol + tx*4],
                      make_float4(vv[0], vv[1], vv[2], vv[3]));
        }
    }
}

__global__ void transpose_kernel(const float* __restrict__ in, float* __restrict__ out,
                                 int R, int C){
    __shared__ float tile[32][33];
    int cb = blockIdx.x*32, rb = blockIdx.y*32;
    int tx = threadIdx.x&31, ty = threadIdx.x>>5;
    #pragma unroll
    for (int j=0;j<32;j+=8)
        tile[ty+j][tx] = in[(size_t)(rb+ty+j)*C + cb+tx];
    __syncthreads();
    #pragma unroll
    for (int j=0;j<32;j+=8)
        out[(size_t)(cb+ty+j)*R + rb+tx] = tile[tx][ty+j];
}

// W_fc [K=1024][N=20000] -> transposed bf16 hi/lo planes [NVP][1024]
__global__ void wtrans_kernel(const float* __restrict__ W){
    __shared__ float tile[32][33];
    int nb = blockIdx.x*32, kb = blockIdx.y*32;
    int tx = threadIdx.x&31, ty = threadIdx.x>>5;
    #pragma unroll
    for (int j=0;j<32;j+=8){
        int k = kb+ty+j, n = nb+tx;
        tile[ty+j][tx] = (n < NV) ? W[(size_t)k*NV + n] : 0.f;
    }
    __syncthreads();
    #pragma unroll
    for (int j=0;j<32;j+=8){
        int n = nb+ty+j, k = kb+tx;
        float v = tile[tx][ty+j];
        __nv_bfloat16 hi = __float2bfloat16(v);
        __nv_bfloat16 lo = __float2bfloat16(v - __bfloat162float(hi));
        g_Whi[(size_t)n*NH + k] = hi;
        g_Wlo[(size_t)n*NH + k] = lo;
    }
}

// g_hall fp32 [M][K] -> bf16 hi/lo planes
__global__ void aconv_kernel(){
    int m = blockIdx.x;
    for (int k=threadIdx.x; k<NH; k+=256){
        float v = g_hall[(size_t)m*NH + k];
        __nv_bfloat16 hi = __float2bfloat16(v);
        __nv_bfloat16 lo = __float2bfloat16(v - __bfloat162float(hi));
        g_Ahi[(size_t)m*NH + k] = hi;
        g_Alo[(size_t)m*NH + k] = lo;
    }
}

__global__ void emb_gatherT_kernel(const float* __restrict__ emb, const int* __restrict__ cap){
    int tb = blockIdx.x;
    int t = tb>>6, b = tb&63;
    int tok = cap[b*NCAP + t];
    const float* src = emb + (size_t)tok*NE;
    float* dst = g_embT + (size_t)t*NE*64;
    for (int e=threadIdx.x; e<NE; e+=256)
        dst[(size_t)e*64 + b] = src[e];
}

// ---------------- launch ----------------
extern "C" void kernel_launch(void* const* d_in, const int* in_sizes, int n_in,
                              void* d_out, int out_size) {
    int o = (n_in >= 22 && in_sizes[2] == 1) ? 1 : 0;
    const float* enc      = (const float*)d_in[0];
    const int*   cap      = (const int*)  d_in[1];
    const float* W_enc    = (const float*)d_in[2+o];
    const float* b_enc    = (const float*)d_in[3+o];
    const float* W_dec    = (const float*)d_in[4+o];
    const float* b_dec    = (const float*)d_in[5+o];
    const float* W_full   = (const float*)d_in[6+o];
    const float* b_full   = (const float*)d_in[7+o];
    const float* emb      = (const float*)d_in[8+o];
    const float* W_ih     = (const float*)d_in[9+o];
    const float* b_ih     = (const float*)d_in[10+o];
    const float* W_hh     = (const float*)d_in[11+o];
    const float* b_hh     = (const float*)d_in[12+o];
    const float* W_init_h = (const float*)d_in[13+o];
    const float* b_init_h = (const float*)d_in[14+o];
    const float* W_init_c = (const float*)d_in[15+o];
    const float* b_init_c = (const float*)d_in[16+o];
    const float* W_fbeta  = (const float*)d_in[17+o];
    const float* b_fbeta  = (const float*)d_in[18+o];
    const float* W_fc     = (const float*)d_in[19+o];
    const float* b_fc     = (const float*)d_in[20+o];

    float* preds = (float*)d_out;
    float* aout  = (out_size >= PRED_SIZE + ALPHA_SIZE) ? (preds + PRED_SIZE) : nullptr;

    float *p_att_enc=nullptr, *p_encT=nullptr;
    __nv_bfloat16 *p_Ahi=nullptr, *p_Alo=nullptr, *p_Whi=nullptr, *p_Wlo=nullptr;
    cudaGetSymbolAddress((void**)&p_att_enc, g_att_enc);
    cudaGetSymbolAddress((void**)&p_encT,    g_encT);
    cudaGetSymbolAddress((void**)&p_Ahi,     g_Ahi);
    cudaGetSymbolAddress((void**)&p_Alo,     g_Alo);
    cudaGetSymbolAddress((void**)&p_Whi,     g_Whi);
    cudaGetSymbolAddress((void**)&p_Wlo,     g_Wlo);

    static int smem_set = 0;
    if (!smem_set){
        cudaFuncSetAttribute(logits_mma, cudaFuncAttributeMaxDynamicSharedMemorySize,
                             2*STAGE);
        smem_set = 1;
    }

    // Setup
    biascat_kernel<<<20,256>>>(b_dec, b_fbeta, b_ih, b_hh);
    mean_kernel<<<dim3(NB,4),128>>>(enc);
    transpose_kernel<<<dim3(NENC/32, NB*NP/32),256>>>(enc, p_encT, NB*NP, NENC);
    gemm_tiled<<<dim3(4,98),256>>>(p_encT, W_enc, b_enc, p_att_enc,
                                   NB*NP, NA, NENC);
    wtrans_kernel<<<dim3(NVP/32, NH/32),256>>>(W_fc);
    lin_init_kernel<<<NB,256>>>();
    init_hc_kernel<<<dim3(NB,4),256>>>(b_init_h, b_init_c);
    emb_gatherT_kernel<<<NT*NB,256>>>(emb, cap);
    init_gemm<<<dim3(8,2),256>>>(W_init_h, W_init_c);

    // Whole recurrence in ONE persistent kernel
    loop_kernel<<<NCTA,256>>>(enc, W_dec, W_fbeta, W_hh, W_full, b_full,
                              W_ih, aout);

    // h -> bf16 split planes
    aconv_kernel<<<NM,256>>>();

    // Tensor-core logits GEMM (mma.sync bf16 split)
    logits_mma<<<dim3(157,12),256, 2*STAGE>>>(p_Ahi, p_Alo, p_Whi, p_Wlo,
                                              b_fc, preds);
}

// round 16
// speedup vs baseline: 1.7161x; 1.0069x over previous
#include <cuda_runtime.h>
#include <cuda_bf16.h>
#include <stdint.h>
#include <math.h>

#define NB   64
#define NP   196
#define NENC 512
#define NE   1024
#define NH   1024
#define NA   512
#define NV   20000
#define NVP  20096         /* NV padded to 157*128 */
#define NT   24
#define NCAP 25
#define NLIN 5120
#define NM   (NT*NB)       /* 1536 */
#define NCTA 148
#define PRED_SIZE (NB*NT*NV)
#define ALPHA_SIZE (NB*NT*NP)

typedef unsigned long long u64;

// ---------------- device scratch (static; no allocations) ----------------
__device__ float g_att_enc[NB*NP*NA];     // 25.7 MB (bias-preloaded)
__device__ float g_encT[NENC*NB*NP];      // 25.7 MB
__device__ float g_meanT[NENC*NB];        // mean transposed [ENC][B]
__device__ float g_htmp[NB*NH];           // h0 row-major (pre-transpose)
__device__ float g_hT[NH*NB];
__device__ float g_c[NB*NH];
__device__ float g_lin[NB*NLIN];
__device__ float g_ctxT[NENC*NB];
__device__ float g_embT[NT*NE*NB];
__device__ float g_biascat[NLIN];
__device__ unsigned g_bar;
// bf16 split planes for mma logits GEMM
__device__ __nv_bfloat16 g_Ahi[NM*NH];
__device__ __nv_bfloat16 g_Alo[NM*NH];
__device__ __nv_bfloat16 g_Whi[(size_t)NVP*NH];
__device__ __nv_bfloat16 g_Wlo[(size_t)NVP*NH];

// ---------------- helpers ----------------
__device__ __forceinline__ u64 pk2(float lo, float hi){
    u64 r; asm("mov.b64 %0,{%1,%2};" : "=l"(r) : "f"(lo), "f"(hi)); return r;
}
__device__ __forceinline__ void fma2(u64 &d, u64 a, u64 b){
    asm("fma.rn.f32x2 %0,%1,%2,%0;" : "+l"(d) : "l"(a), "l"(b));
}
__device__ __forceinline__ float2 up2(u64 v){
    float2 f; asm("mov.b64 {%0,%1},%2;" : "=f"(f.x), "=f"(f.y) : "l"(v)); return f;
}
__device__ __forceinline__ float sigm(float x){ return 1.0f/(1.0f+expf(-x)); }
__device__ __forceinline__ unsigned su(const void* p){
    return (unsigned)__cvta_generic_to_shared(p);
}
__device__ __forceinline__ void cp16(unsigned saddr, const void* g){
    asm volatile("cp.async.cg.shared.global [%0],[%1],16;" :: "r"(saddr), "l"(g));
}
__device__ __forceinline__ void cp_commit(){ asm volatile("cp.async.commit_group;"); }
__device__ __forceinline__ void cp_wait1(){ asm volatile("cp.async.wait_group 1;" ::: "memory"); }

// global barrier
__device__ __forceinline__ void gbar(unsigned &tgt){
    __syncthreads();
    __threadfence();
    if (threadIdx.x == 0){
        atomicAdd(&g_bar, 1u);
        while (atomicAdd(&g_bar, 0u) < tgt) __nanosleep(64);
    }
    __syncthreads();
    __threadfence();
    tgt += NCTA;
}

// ---------------- warp-MMA primitives (base ISA) ----------------
__device__ __forceinline__ void ldsm4(uint32_t &r0, uint32_t &r1, uint32_t &r2,
                                      uint32_t &r3, uint32_t addr){
    asm volatile("ldmatrix.sync.aligned.m8n8.x4.shared.b16 {%0,%1,%2,%3}, [%4];"
        : "=r"(r0), "=r"(r1), "=r"(r2), "=r"(r3) : "r"(addr));
}
__device__ __forceinline__ void mma16816(float* d, const uint32_t* a, uint32_t b0, uint32_t b1){
    asm volatile("mma.sync.aligned.m16n8k16.row.col.f32.bf16.bf16.f32 "
        "{%0,%1,%2,%3},{%4,%5,%6,%7},{%8,%9},{%0,%1,%2,%3};"
        : "+f"(d[0]), "+f"(d[1]), "+f"(d[2]), "+f"(d[3])
        : "r"(a[0]), "r"(a[1]), "r"(a[2]), "r"(a[3]), "r"(b0), "r"(b1));
}

// =====================================================================
// dev_gemm64: dst(+bias preloaded) += AT^T[64,Kc] @ W-chunk, atomicAdd.
// AT is [K][lda-strided], A read = 2 broadcast LDS.128. KT k-tiles of 16.
// =====================================================================
__device__ __forceinline__ void dev_gemm64(
    float* sm, const float* __restrict__ AT, int lda, int ak0,
    const float* __restrict__ W, int ldw, int wk0, int wcol,
    float* __restrict__ dst, int ldd, int dcol, int KT)
{
    float (*As)[16][64]  = (float(*)[16][64])sm;
    float (*Bs)[16][128] = (float(*)[16][128])(sm + 2048);
    const int tid = threadIdx.x;
    const int ty = tid>>5, tx = tid&31;

    u64 acc[8][2];
    #pragma unroll
    for (int i=0;i<8;i++){ acc[i][0]=0ULL; acc[i][1]=0ULL; }

    auto load = [&](int kt, int buf){
        int k = kt<<4;
        {
            int r = tid>>4, qq = tid&15;
            cp16(su(&As[buf][r][qq*4]), &AT[(size_t)(ak0+k+r)*lda + qq*4]);
        }
        #pragma unroll
        for (int rep=0;rep<2;rep++){
            int i = tid + rep*256;
            int r = i>>5, c4 = i&31;
            cp16(su(&Bs[buf][r][c4*4]), &W[(size_t)(wk0+k+r)*ldw + wcol + c4*4]);
        }
    };

    load(0,0); cp_commit();
    for (int kt=0; kt<KT; kt++){
        if (kt+1 < KT) load(kt+1, (kt+1)&1);
        cp_commit();
        cp_wait1();
        __syncthreads();
        const int buf = kt&1;
        #pragma unroll
        for (int kk=0;kk<16;kk++){
            float4 a0 = *(const float4*)&As[buf][kk][ty*8];
            float4 a1 = *(const float4*)&As[buf][kk][ty*8+4];
            u64 a2[8];
            a2[0]=pk2(a0.x,a0.x); a2[1]=pk2(a0.y,a0.y);
            a2[2]=pk2(a0.z,a0.z); a2[3]=pk2(a0.w,a0.w);
            a2[4]=pk2(a1.x,a1.x); a2[5]=pk2(a1.y,a1.y);
            a2[6]=pk2(a1.z,a1.z); a2[7]=pk2(a1.w,a1.w);
            ulonglong2 bt = *(const ulonglong2*)&Bs[buf][kk][tx*4];
            #pragma unroll
            for (int i=0;i<8;i++){ fma2(acc[i][0], a2[i], bt.x); fma2(acc[i][1], a2[i], bt.y); }
        }
        __syncthreads();
    }

    #pragma unroll
    for (int i=0;i<8;i++){
        int m = ty*8 + i;
        float* dp = dst + (size_t)m*ldd + dcol + tx*4;
        float2 v0 = up2(acc[i][0]), v1 = up2(acc[i][1]);
        atomicAdd((float4*)dp, make_float4(v0.x, v0.y, v1.x, v1.y));
    }
}

// ---------------- att phase body ----------------
__device__ void att_body(float* sm, const float* __restrict__ enc,
                         const float* __restrict__ Wfull,
                         const float* __restrict__ bfull,
                         float* __restrict__ aout, int t, int b)
{
    float* s_ad = sm;
    float* s_w  = sm + 512;
    float* s_en = sm + 1024;
    float* s_al = sm + 1232;
    float* red  = sm + 1440;
    float* s_ms = sm + 1448;
    int tid = threadIdx.x, warp = tid>>5, lane = tid&31;

    for (int i=tid; i<NA; i+=256){
        s_ad[i] = g_lin[b*NLIN + i];
        s_w[i]  = Wfull[i];
    }
    __syncthreads();

    float bf = bfull[0];
    for (int p=warp; p<NP; p+=8){
        const float* ae = g_att_enc + (size_t)(b*NP + p)*NA;
        float s = 0.f;
        #pragma unroll
        for (int u=0; u<16; u++){
            int a = lane + u*32;
            s += fmaxf(ae[a] + s_ad[a], 0.f) * s_w[a];
        }
        #pragma unroll
        for (int o=16;o;o>>=1) s += __shfl_xor_sync(0xffffffffu, s, o);
        if (!lane) s_en[p] = s + bf;
    }
    __syncthreads();

    float v = (tid<NP) ? s_en[tid] : -3.4e38f;
    float m = v;
    #pragma unroll
    for (int o=16;o;o>>=1) m = fmaxf(m, __shfl_xor_sync(0xffffffffu, m, o));
    if (!lane) red[warp] = m;
    __syncthreads();
    if (tid==0){
        float mm = red[0];
        #pragma unroll
        for (int i=1;i<8;i++) mm = fmaxf(mm, red[i]);
        s_ms[0] = mm;
    }
    __syncthreads();
    float e = (tid<NP) ? expf(v - s_ms[0]) : 0.f;
    float s = e;
    #pragma unroll
    for (int o=16;o;o>>=1) s += __shfl_xor_sync(0xffffffffu, s, o);
    if (!lane) red[warp] = s;
    __syncthreads();
    if (tid==0){
        float ss = 0.f;
        #pragma unroll
        for (int i=0;i<8;i++) ss += red[i];
        s_ms[1] = ss;
    }
    __syncthreads();
    float inv = 1.0f/s_ms[1];
    if (tid < NP){
        float a = e*inv;
        s_al[tid] = a;
        if (aout) aout[((size_t)b*NT + t)*NP + tid] = a;
    }
    __syncthreads();

    int e0 = tid*2;
    const float* pbase = enc + (size_t)b*NP*NENC + e0;
    float c0=0.f, c1=0.f;
    #pragma unroll 4
    for (int p=0;p<NP;p++){
        float2 w = *(const float2*)(pbase + (size_t)p*NENC);
        float al = s_al[p];
        c0 += al*w.x; c1 += al*w.y;
    }
    float g0 = sigm(g_lin[b*NLIN + 512 + e0]);
    float g1 = sigm(g_lin[b*NLIN + 512 + e0 + 1]);
    g_ctxT[(size_t)e0*64 + b]     = g0*c0;
    g_ctxT[(size_t)(e0+1)*64 + b] = g1*c1;
}

// ---------------- lstm phase body (writes bf16 split planes directly) --
__device__ void lstm_body(int b, int t){
    int tid = threadIdx.x;
    const float* L = g_lin + (size_t)b*NLIN + 1024;
    for (int n=tid; n<NH; n+=256){
        float iv = sigm(L[n]);
        float fv = sigm(L[1024+n]);
        float gv = tanhf(L[2048+n]);
        float ov = sigm(L[3072+n]);
        float c = fv*g_c[b*NH+n] + iv*gv;
        float h = ov*tanhf(c);
        g_c[b*NH+n] = c;
        g_hT[(size_t)n*64 + b] = h;
        size_t mi = (size_t)(t*NB + b)*NH + n;
        __nv_bfloat16 hi = __float2bfloat16(h);
        g_Ahi[mi] = hi;
        g_Alo[mi] = __float2bfloat16(h - __bfloat162float(hi));
    }
    __syncthreads();
    for (int i=tid; i<NLIN; i+=256) g_lin[b*NLIN + i] = g_biascat[i];
}

// =====================================================================
// Persistent kernel: pre-phases (att_enc GEMM + h0/c0 init + h0 transpose)
// then the 24-step recurrence. grid = 148 CTAs x 256 threads.
// =====================================================================
__global__ void __launch_bounds__(256) loop_kernel(
    const float* __restrict__ enc,   const float* __restrict__ W_enc,
    const float* __restrict__ W_init_h, const float* __restrict__ W_init_c,
    const float* __restrict__ W_dec, const float* __restrict__ W_fbeta,
    const float* __restrict__ W_hh,  const float* __restrict__ W_full,
    const float* __restrict__ b_full,const float* __restrict__ W_ih,
    float* __restrict__ aout)
{
    __shared__ __align__(16) float sm[6144];
    const int bid = blockIdx.x;
    const int tid = threadIdx.x;
    unsigned tgt = NCTA;

    // pre-phase 1: att_enc = encT^T @ W_enc (+bias preloaded), 784 units;
    //              h0/c0 = meanT^T @ W_init (+bias preloaded), 16 units.
    for (int u = bid; u < 800; u += NCTA){
        if (u < 784){
            int r64 = u>>2, cb = u&3;
            dev_gemm64(sm, g_encT + r64*64, NB*NP, 0,
                       W_enc, 512, 0, cb*128,
                       g_att_enc + (size_t)r64*64*512, 512, cb*128, 32);
        } else if (u < 792){
            int nt = u-784;
            dev_gemm64(sm, g_meanT, 64, 0, W_init_h, 1024, 0, nt*128,
                       g_htmp, 1024, nt*128, 32);
        } else {
            int nt = u-792;
            dev_gemm64(sm, g_meanT, 64, 0, W_init_c, 1024, 0, nt*128,
                       g_c, 1024, nt*128, 32);
        }
    }
    gbar(tgt);

    // pre-phase 2: transpose h0 (64x1024) -> g_hT (1024x64); 64 tiles.
    if (bid < 64){
        float (*tile)[33] = (float(*)[33])sm;
        int rb = (bid&1)*32, cb = (bid>>1)*32;
        int tx = tid&31, ty = tid>>5;
        #pragma unroll
        for (int j=0;j<32;j+=8)
            tile[ty+j][tx] = g_htmp[(size_t)(rb+ty+j)*NH + cb+tx];
        __syncthreads();
        #pragma unroll
        for (int j=0;j<32;j+=8)
            g_hT[(size_t)(cb+ty+j)*64 + rb+tx] = tile[tx][ty+j];
    }
    gbar(tgt);

    // 24-step recurrence
    for (int t=0; t<NT; t++){
        for (int u = bid; u < 320; u += NCTA){
            int nt = u % 40, kz = u / 40;
            int nc = nt*128;
            const float* W; int wcol, ldw;
            if (nc < 512)       { W=W_dec;   wcol=nc;      ldw=512;  }
            else if (nc < 1024) { W=W_fbeta; wcol=nc-512;  ldw=512;  }
            else                { W=W_hh;    wcol=nc-1024; ldw=4096; }
            dev_gemm64(sm, g_hT, 64, kz*128, W, ldw, kz*128, wcol,
                       g_lin, NLIN, nc, 8);
        }
        gbar(tgt);

        if (bid < 64){
            att_body(sm, enc, W_full, b_full, aout, t, bid);
        } else {
            for (int u = bid-64; u < 128; u += (NCTA-64)){
                int nt = u & 31, kz = u >> 5;
                dev_gemm64(sm, g_embT + (size_t)t*NE*64, 64, kz*256,
                           W_ih, 4096, kz*256, nt*128,
                           g_lin, NLIN, 1024 + nt*128, 16);
            }
        }
        gbar(tgt);

        if (bid < 128){
            int nt = bid & 31, kz = bid >> 5;
            dev_gemm64(sm, g_ctxT, 64, kz*128,
                       W_ih, 4096, 1024 + kz*128, nt*128,
                       g_lin, NLIN, 1024 + nt*128, 8);
        }
        gbar(tgt);

        if (bid < 64) lstm_body(bid, t);
        gbar(tgt);
    }
}

// =====================================================================
// Logits GEMM via mma.sync bf16 split (unchanged from R15).
// =====================================================================
#define PLANE 10240
#define STAGE (4*PLANE)

__global__ void __launch_bounds__(256) logits_mma(
    const __nv_bfloat16* __restrict__ Ahi, const __nv_bfloat16* __restrict__ Alo,
    const __nv_bfloat16* __restrict__ Bhi, const __nv_bfloat16* __restrict__ Blo,
    const float* __restrict__ bias, float* __restrict__ preds)
{
    extern __shared__ char dsm[];
    const int tid = threadIdx.x, wid = tid>>5, lane = tid&31;
    const int bm = blockIdx.y*128, bn = blockIdx.x*128;
    const int wm = wid>>2, wn = wid&3;
    const uint32_t sbase = su(dsm);

    float acc[4][4][4];
    #pragma unroll
    for (int i=0;i<4;i++)
        #pragma unroll
        for (int j=0;j<4;j++)
            #pragma unroll
            for (int r=0;r<4;r++) acc[i][j][r]=0.f;

    auto ld_stage = [&](int c, int s){
        uint32_t st = sbase + s*STAGE;
        int k0 = c*32;
        #pragma unroll
        for (int it=0; it<8; ++it){
            int idx = tid + it*256;
            int p = idx >> 9;
            int rj = idx & 511;
            int r = rj >> 2, j = rj & 3;
            const __nv_bfloat16* src;
            if      (p==0) src = Ahi + (size_t)(bm+r)*NH + k0 + j*8;
            else if (p==1) src = Alo + (size_t)(bm+r)*NH + k0 + j*8;
            else if (p==2) src = Bhi + (size_t)(bn+r)*NH + k0 + j*8;
            else           src = Blo + (size_t)(bn+r)*NH + k0 + j*8;
            cp16(st + p*PLANE + r*80 + j*16, src);
        }
    };

    ld_stage(0,0); cp_commit();

    const int q  = lane>>3, i8 = lane&7;
    const int rq = (q&1)*8 + i8;
    const int kq = (q>>1)*16;

    for (int c=0; c<32; c++){
        if (c+1 < 32) ld_stage(c+1, (c+1)&1);
        cp_commit();
        cp_wait1();
        __syncthreads();
        const uint32_t st = sbase + (c&1)*STAGE;
        const uint32_t aO = st, alO = st+PLANE, bO = st+2*PLANE, blO = st+3*PLANE;

        #pragma unroll
        for (int kh=0; kh<2; kh++){
            uint32_t Ah[4][4], Al[4][4], Bh[2][4], Bl[2][4];
            #pragma unroll
            for (int mt=0; mt<4; mt++){
                uint32_t off = (uint32_t)(wm*64 + mt*16 + rq)*80 + kh*32 + kq;
                ldsm4(Ah[mt][0],Ah[mt][1],Ah[mt][2],Ah[mt][3], aO  + off);
                ldsm4(Al[mt][0],Al[mt][1],Al[mt][2],Al[mt][3], alO + off);
            }
            #pragma unroll
            for (int g=0; g<2; g++){
                uint32_t off = (uint32_t)(wn*32 + g*16 + rq)*80 + kh*32 + kq;
                ldsm4(Bh[g][0],Bh[g][1],Bh[g][2],Bh[g][3], bO  + off);
                ldsm4(Bl[g][0],Bl[g][1],Bl[g][2],Bl[g][3], blO + off);
            }
            #pragma unroll
            for (int mt=0; mt<4; mt++){
                #pragma unroll
                for (int nt=0; nt<4; nt++){
                    int g = nt>>1, sel = nt&1;
                    mma16816(acc[mt][nt], Ah[mt], Bh[g][sel],   Bh[g][2+sel]);
                    mma16816(acc[mt][nt], Ah[mt], Bl[g][sel],   Bl[g][2+sel]);
                    mma16816(acc[mt][nt], Al[mt], Bh[g][sel],   Bh[g][2+sel]);
                }
            }
        }
        __syncthreads();
    }

    #pragma unroll
    for (int mt=0; mt<4; mt++){
        #pragma unroll
        for (int nt=0; nt<4; nt++){
            int n0 = bn + wn*32 + nt*8 + (lane&3)*2;
            if (n0 >= NV) continue;
            float b0 = bias[n0], b1 = bias[n0+1];
            int r0 = bm + wm*64 + mt*16 + (lane>>2);
            #pragma unroll
            for (int h=0; h<2; h++){
                int m = r0 + h*8;
                int b = m & 63, t = m >> 6;
                size_t rb = ((size_t)(b*NT + t))*NV + n0;
                float2 o;
                o.x = acc[mt][nt][h*2+0] + b0;
                o.y = acc[mt][nt][h*2+1] + b1;
                *(float2*)&preds[rb] = o;
            }
        }
    }
}

// =====================================================================
// mega_setup: all independent init in ONE launch (decode by blockIdx).
// [0,20)=biascat+bar-reset [20,84)=lin_init [84,148)=meanT
// [148,404)=h0/c0 bias preload [404,1940)=embT gather
// [1940,3508)=att_enc bias preload
// =====================================================================
__global__ void __launch_bounds__(256) mega_setup(
    const float* __restrict__ b_dec, const float* __restrict__ b_fb,
    const float* __restrict__ b_ih,  const float* __restrict__ b_hh,
    const float* __restrict__ enc,   const float* __restrict__ b_enc,
    const float* __restrict__ bh,    const float* __restrict__ bc,
    const float* __restrict__ emb,   const int* __restrict__ cap)
{
    int blk = blockIdx.x, tid = threadIdx.x;
    if (blk < 20){
        if (blk==0 && tid==0) g_bar = 0u;
        int i = blk*256 + tid;
        if (i < 512)       g_biascat[i] = b_dec[i];
        else if (i < 1024) g_biascat[i] = b_fb[i-512];
        else if (i < NLIN) g_biascat[i] = b_ih[i-1024] + b_hh[i-1024];
    } else if (blk < 84){
        int b = blk-20;
        for (int i=tid; i<NLIN; i+=256) g_lin[b*NLIN + i] = g_biascat[i];
    } else if (blk < 148){
        int b = blk-84;
        for (int e=tid; e<NENC; e+=256){
            const float* p = enc + (size_t)b*NP*NENC + e;
            float s = 0.f;
            #pragma unroll 4
            for (int i=0;i<NP;i++) s += p[(size_t)i*NENC];
            g_meanT[(size_t)e*64 + b] = s * (1.0f/(float)NP);
        }
    } else if (blk < 404){
        int idx = blk-148;
        int b = idx>>2, n = (idx&3)*256 + tid;
        g_htmp[(size_t)b*NH + n] = bh[n];
        g_c[(size_t)b*NH + n]    = bc[n];
    } else if (blk < 1940){
        int tb = blk-404;
        int t = tb>>6, b = tb&63;
        int tok = cap[b*NCAP + t];
        const float* src = emb + (size_t)tok*NE;
        float* dst = g_embT + (size_t)t*NE*64;
        for (int e=tid; e<NE; e+=256)
            dst[(size_t)e*64 + b] = src[e];
    } else {
        int idx = blk-1940;                 // 8 rows per block
        for (int i=tid; i<8*512; i+=256){
            int rl = i>>9, c = i&511;
            g_att_enc[(size_t)(idx*8 + rl)*512 + c] = b_enc[c];
        }
    }
}

__global__ void transpose_kernel(const float* __restrict__ in, float* __restrict__ out,
                                 int R, int C){
    __shared__ float tile[32][33];
    int cb = blockIdx.x*32, rb = blockIdx.y*32;
    int tx = threadIdx.x&31, ty = threadIdx.x>>5;
    #pragma unroll
    for (int j=0;j<32;j+=8)
        tile[ty+j][tx] = in[(size_t)(rb+ty+j)*C + cb+tx];
    __syncthreads();
    #pragma unroll
    for (int j=0;j<32;j+=8)
        out[(size_t)(cb+ty+j)*R + rb+tx] = tile[tx][ty+j];
}

// W_fc [K=1024][N=20000] -> transposed bf16 hi/lo planes [NVP][1024]
__global__ void wtrans_kernel(const float* __restrict__ W){
    __shared__ float tile[32][33];
    int nb = blockIdx.x*32, kb = blockIdx.y*32;
    int tx = threadIdx.x&31, ty = threadIdx.x>>5;
    #pragma unroll
    for (int j=0;j<32;j+=8){
        int k = kb+ty+j, n = nb+tx;
        tile[ty+j][tx] = (n < NV) ? W[(size_t)k*NV + n] : 0.f;
    }
    __syncthreads();
    #pragma unroll
    for (int j=0;j<32;j+=8){
        int n = nb+ty+j, k = kb+tx;
        float v = tile[tx][ty+j];
        __nv_bfloat16 hi = __float2bfloat16(v);
        __nv_bfloat16 lo = __float2bfloat16(v - __bfloat162float(hi));
        g_Whi[(size_t)n*NH + k] = hi;
        g_Wlo[(size_t)n*NH + k] = lo;
    }
}

// ---------------- launch ----------------
extern "C" void kernel_launch(void* const* d_in, const int* in_sizes, int n_in,
                              void* d_out, int out_size) {
    int o = (n_in >= 22 && in_sizes[2] == 1) ? 1 : 0;
    const float* enc      = (const float*)d_in[0];
    const int*   cap      = (const int*)  d_in[1];
    const float* W_enc    = (const float*)d_in[2+o];
    const float* b_enc    = (const float*)d_in[3+o];
    const float* W_dec    = (const float*)d_in[4+o];
    const float* b_dec    = (const float*)d_in[5+o];
    const float* W_full   = (const float*)d_in[6+o];
    const float* b_full   = (const float*)d_in[7+o];
    const float* emb      = (const float*)d_in[8+o];
    const float* W_ih     = (const float*)d_in[9+o];
    const float* b_ih     = (const float*)d_in[10+o];
    const float* W_hh     = (const float*)d_in[11+o];
    const float* b_hh     = (const float*)d_in[12+o];
    const float* W_init_h = (const float*)d_in[13+o];
    const float* b_init_h = (const float*)d_in[14+o];
    const float* W_init_c = (const float*)d_in[15+o];
    const float* b_init_c = (const float*)d_in[16+o];
    const float* W_fbeta  = (const float*)d_in[17+o];
    const float* b_fbeta  = (const float*)d_in[18+o];
    const float* W_fc     = (const float*)d_in[19+o];
    const float* b_fc     = (const float*)d_in[20+o];

    float* preds = (float*)d_out;
    float* aout  = (out_size >= PRED_SIZE + ALPHA_SIZE) ? (preds + PRED_SIZE) : nullptr;

    float *p_encT=nullptr;
    __nv_bfloat16 *p_Ahi=nullptr, *p_Alo=nullptr, *p_Whi=nullptr, *p_Wlo=nullptr;
    cudaGetSymbolAddress((void**)&p_encT, g_encT);
    cudaGetSymbolAddress((void**)&p_Ahi,  g_Ahi);
    cudaGetSymbolAddress((void**)&p_Alo,  g_Alo);
    cudaGetSymbolAddress((void**)&p_Whi,  g_Whi);
    cudaGetSymbolAddress((void**)&p_Wlo,  g_Wlo);

    static int smem_set = 0;
    if (!smem_set){
        cudaFuncSetAttribute(logits_mma, cudaFuncAttributeMaxDynamicSharedMemorySize,
                             2*STAGE);
        smem_set = 1;
    }

    // launch 0: all independent setup
    mega_setup<<<3508,256>>>(b_dec, b_fbeta, b_ih, b_hh, enc, b_enc,
                             b_init_h, b_init_c, emb, cap);
    // launch 1: W_fc -> bf16 split planes
    wtrans_kernel<<<dim3(NVP/32, NH/32),256>>>(W_fc);
    // launch 2: encoder transpose
    transpose_kernel<<<dim3(NENC/32, NB*NP/32),256>>>(enc, p_encT, NB*NP, NENC);
    // launch 3 (ncu-profiled slot): pre-phases + full recurrence
    loop_kernel<<<NCTA,256>>>(enc, W_enc, W_init_h, W_init_c,
                              W_dec, W_fbeta, W_hh, W_full, b_full,
                              W_ih, aout);
    // launch 4: logits GEMM (mma.sync bf16 split)
    logits_mma<<<dim3(157,12),256, 2*STAGE>>>(p_Ahi, p_Alo, p_Whi, p_Wlo,
                                              b_fc, preds);
}